// round 10
// baseline (speedup 1.0000x reference)
#include <cuda_runtime.h>
#include <cstdint>
#include <math.h>

// ---------------------------------------------------------------------------
// Problem constants
// ---------------------------------------------------------------------------
#define B_   4
#define S_   2048
#define H_   1024
#define NH_  16
#define HD_  64
#define E_   4096
#define M_   (B_ * S_)          // 8192 tokens
#define QKV_N (3 * H_)          // 3072

// ---------------------------------------------------------------------------
// Scratch (device globals — no allocation allowed)
// ---------------------------------------------------------------------------
__device__ float g_h  [M_ * H_];     // ln1 output (perm+tf32)
__device__ float g_qkv[M_ * QKV_N];  // qkv: Q,K perm+tf32; V plain tf32
__device__ float g_o  [M_ * H_];     // attention output (perm+tf32)
__device__ float g_x2 [M_ * H_];     // x + attn@Wo + bo (plain fp32)
__device__ float g_h2 [M_ * H_];     // ln2 output (perm+tf32)
__device__ float g_a  [M_ * E_];     // gelu(fc1) (perm+tf32)
// transposed+rounded weights: [N][K] with k-permuted 16-blocks
__device__ float g_wqkvT[QKV_N * H_];
__device__ float g_woT  [H_ * H_];
__device__ float g_w1T  [E_ * H_];
__device__ float g_w2T  [H_ * E_];

// ---------------------------------------------------------------------------
// Helpers
// ---------------------------------------------------------------------------
__device__ __forceinline__ uint32_t smem_u32(const void* p) {
    uint32_t a;
    asm("{ .reg .u64 t; cvta.to.shared.u64 t, %1; cvt.u32.u64 %0, t; }"
        : "=r"(a) : "l"(p));
    return a;
}
// tf32 round-to-nearest (rna); result returned as float bits
__device__ __forceinline__ float tf32r(float x) {
    uint32_t r;
    asm("cvt.rna.tf32.f32 %0, %1;" : "=r"(r) : "f"(x));
    return __uint_as_float(r);
}
// position of element k within the k-permuted layout (within 16-blocks)
__device__ __forceinline__ int pj(int k) {
    return (k & ~15) | ((k & 3) << 2) | ((k >> 2) & 3);
}

__device__ __forceinline__ void mma_tf32(float* c, const uint32_t* a, const uint32_t* b) {
    asm volatile(
        "mma.sync.aligned.m16n8k8.row.col.f32.tf32.tf32.f32 "
        "{%0,%1,%2,%3}, {%4,%5,%6,%7}, {%8,%9}, {%0,%1,%2,%3};"
        : "+f"(c[0]), "+f"(c[1]), "+f"(c[2]), "+f"(c[3])
        : "r"(a[0]), "r"(a[1]), "r"(a[2]), "r"(a[3]), "r"(b[0]), "r"(b[1]));
}

#define CP_ASYNC16(saddr, gptr) \
    asm volatile("cp.async.cg.shared.global [%0], [%1], 16;" \
        :: "r"(saddr), "l"(gptr) : "memory")
#define CP_COMMIT() asm volatile("cp.async.commit_group;" ::: "memory")

// ---------------------------------------------------------------------------
// Weight transpose + tf32-round + k-permute:  W[K][N] -> WT[N][K]
// ---------------------------------------------------------------------------
__global__ __launch_bounds__(256) void wtrans(
    const float* __restrict__ W, float* __restrict__ WT, int K, int N)
{
    __shared__ float t[32][33];
    const int n0 = blockIdx.x * 32, k0 = blockIdx.y * 32;
    const int tx = threadIdx.x & 31, ty = threadIdx.x >> 5;
#pragma unroll
    for (int r = 0; r < 4; r++)
        t[ty + 8 * r][tx] = W[(size_t)(k0 + ty + 8 * r) * N + n0 + tx];
    __syncthreads();
#pragma unroll
    for (int r = 0; r < 4; r++) {
        const int n = n0 + ty + 8 * r;
        const int k = k0 + tx;
        WT[(size_t)n * K + pj(k)] = tf32r(t[tx][ty + 8 * r]);
    }
}

// ---------------------------------------------------------------------------
// TF32 tensor-core GEMM v5: 128x128 CTA, BK=32 (two 16-blocks), 128 threads,
// 4 warps (2m x 2n), warp tile 64x64. 3-stage cp.async (32KB/stage),
// 2 CTAs/SM. One __syncthreads per 32-K. 16 LDS.128 : 64 HMMA per warp/kb.
// mode 1: bias+residual (plain out); mode 2: bias+GELU (perm+tf32 out);
// mode 3: bias, QKV layout (cols<2048 perm+tf32, else plain tf32)
// ---------------------------------------------------------------------------
#define A16 8192                         // one 16-block: 128 rows x 16 floats
#define STAGE_BYTES (4 * A16)            // A(2 blocks) + B(2 blocks) = 32KB
#define GEMM_SMEM   (3 * STAGE_BYTES)    // 98304 per CTA

__global__ __launch_bounds__(128, 2) void gemm_mma(
    const float* __restrict__ A, const float* __restrict__ BT,
    const float* __restrict__ bias, const float* __restrict__ R,
    float* __restrict__ C, int M, int N, int K, int mode)
{
    extern __shared__ char smem[];
    const int tid = threadIdx.x;
    const int wid = tid >> 5, lane = tid & 31;
    const int gID = lane >> 2, tIG = lane & 3;
    const int warp_m = wid & 1, warp_n = wid >> 1;   // 2 x 2
    const int brow = blockIdx.y * 128, bcol = blockIdx.x * 128;
    const uint32_t sb = smem_u32(smem);

    // loader: row-base = tid>>3 (0..15), chunk = tid&7 (16B, k-contiguous row)
    const int lrow = tid >> 3;
    const int lch  = tid & 7;
    const float* Ag = A  + (size_t)(brow + lrow) * K + lch * 4;
    const float* Bg = BT + (size_t)(bcol + lrow) * K + lch * 4;
    const uint32_t aoff = (uint32_t)((lch >> 2) * A16 + lrow * 64 + (lch & 3) * 16);
    const uint32_t boff = aoff + 2 * A16;

    float acc[4][8][4];
#pragma unroll
    for (int i = 0; i < 4; i++)
#pragma unroll
        for (int j = 0; j < 8; j++)
#pragma unroll
            for (int t = 0; t < 4; t++) acc[i][j][t] = 0.f;

    const int nt_tiles = K >> 5;

    auto issue = [&](int kt) {
        const uint32_t st = sb + (uint32_t)(kt % 3) * STAGE_BYTES;
        const float* ga = Ag + kt * 32;
        const float* gb = Bg + kt * 32;
#pragma unroll
        for (int p = 0; p < 8; p++) {
            CP_ASYNC16(st + aoff + p * 1024, ga + (size_t)(p * 16) * K);
            CP_ASYNC16(st + boff + p * 1024, gb + (size_t)(p * 16) * K);
        }
        CP_COMMIT();
    };

    issue(0); issue(1);

    const int m_base = warp_m * 64;
    const int n_base = warp_n * 64;

    for (int kt = 0; kt < nt_tiles; kt++) {
        if (kt + 1 < nt_tiles) asm volatile("cp.async.wait_group 1;" ::: "memory");
        else                   asm volatile("cp.async.wait_group 0;" ::: "memory");
        __syncthreads();
        // all warps done reading buffer (kt+2)%3 (used in iter kt-1) -> refill
        if (kt + 2 < nt_tiles) issue(kt + 2);

        const char* stage = smem + (size_t)(kt % 3) * STAGE_BYTES;
#pragma unroll
        for (int kb = 0; kb < 2; kb++) {
            const uint32_t* as = (const uint32_t*)(stage + kb * A16);
            const uint32_t* bs = (const uint32_t*)(stage + 2 * A16 + kb * A16);

            uint4 av0[4], av1[4], bv[8];
#pragma unroll
            for (int mt = 0; mt < 4; mt++) {
                const uint32_t* p = as + (m_base + mt * 16 + gID) * 16 + tIG * 4;
                av0[mt] = *(const uint4*)p;
                av1[mt] = *(const uint4*)(p + 128);
            }
#pragma unroll
            for (int nt = 0; nt < 8; nt++)
                bv[nt] = *(const uint4*)(bs + (n_base + nt * 8 + gID) * 16 + tIG * 4);

#pragma unroll
            for (int mt = 0; mt < 4; mt++) {
                const uint32_t aa0[4] = {av0[mt].x, av1[mt].x, av0[mt].y, av1[mt].y};
                const uint32_t aa1[4] = {av0[mt].z, av1[mt].z, av0[mt].w, av1[mt].w};
#pragma unroll
                for (int nt = 0; nt < 8; nt++) {
                    const uint32_t bb0[2] = {bv[nt].x, bv[nt].y};
                    const uint32_t bb1[2] = {bv[nt].z, bv[nt].w};
                    mma_tf32(acc[mt][nt], aa0, bb0);
                    mma_tf32(acc[mt][nt], aa1, bb1);
                }
            }
        }
    }

    // --- epilogue ---
#pragma unroll
    for (int mt = 0; mt < 4; mt++) {
#pragma unroll
        for (int half = 0; half < 2; half++) {
            const int row = brow + m_base + mt * 16 + gID + half * 8;
            float* crow = C + (size_t)row * N;
            const float* rrow = (mode == 1) ? (R + (size_t)row * N) : nullptr;
#pragma unroll
            for (int nt = 0; nt < 8; nt++) {
                const int col = bcol + n_base + nt * 8 + tIG * 2;
                float v0 = acc[mt][nt][half * 2 + 0];
                float v1 = acc[mt][nt][half * 2 + 1];
                const float2 bb = *(const float2*)(bias + col);
                v0 += bb.x; v1 += bb.y;
                if (mode == 1) {
                    const float2 rr = *(const float2*)(rrow + col);
                    v0 += rr.x; v1 += rr.y;
                    *(float2*)(crow + col) = make_float2(v0, v1);
                } else if (mode == 2) {
                    v0 = 0.5f * v0 * (1.f + erff(v0 * 0.70710678118654752f));
                    v1 = 0.5f * v1 * (1.f + erff(v1 * 0.70710678118654752f));
                    crow[pj(col)]     = tf32r(v0);
                    crow[pj(col + 1)] = tf32r(v1);
                } else { // mode 3: QKV layout
                    if (col < 2 * H_) {
                        crow[pj(col)]     = tf32r(v0);
                        crow[pj(col + 1)] = tf32r(v1);
                    } else {
                        *(float2*)(crow + col) = make_float2(tf32r(v0), tf32r(v1));
                    }
                }
            }
        }
    }
}

// ---------------------------------------------------------------------------
// LayerNorm: one block per row of 1024; output tf32-rounded + k-permuted
// ---------------------------------------------------------------------------
__global__ __launch_bounds__(256) void ln_kernel(
    const float* __restrict__ x, const float* __restrict__ w,
    const float* __restrict__ b, float* __restrict__ out)
{
    const int row = blockIdx.x;
    const int tid = threadIdx.x;
    const float* xr = x + (size_t)row * H_;

    float v[4];
    float s = 0.f, s2 = 0.f;
#pragma unroll
    for (int i = 0; i < 4; i++) {
        v[i] = xr[tid + 256 * i];
        s += v[i];
        s2 += v[i] * v[i];
    }
#pragma unroll
    for (int off = 16; off > 0; off >>= 1) {
        s  += __shfl_xor_sync(0xffffffffu, s,  off);
        s2 += __shfl_xor_sync(0xffffffffu, s2, off);
    }
    __shared__ float red[8], red2[8];
    const int wid = tid >> 5, lane = tid & 31;
    if (lane == 0) { red[wid] = s; red2[wid] = s2; }
    __syncthreads();
    if (tid < 32) {
        float a = (tid < 8) ? red[tid]  : 0.f;
        float c = (tid < 8) ? red2[tid] : 0.f;
#pragma unroll
        for (int off = 4; off > 0; off >>= 1) {
            a += __shfl_xor_sync(0xffffffffu, a, off);
            c += __shfl_xor_sync(0xffffffffu, c, off);
        }
        if (tid == 0) { red[0] = a; red2[0] = c; }
    }
    __syncthreads();
    const float mu  = red[0] * (1.f / H_);
    const float var = red2[0] * (1.f / H_) - mu * mu;
    const float rstd = rsqrtf(var + 1e-5f);

    float* orow = out + (size_t)row * H_;
#pragma unroll
    for (int i = 0; i < 4; i++) {
        const int c = tid + 256 * i;
        orow[pj(c)] = tf32r((v[i] - mu) * rstd * w[c] + b[c]);
    }
}

// ---------------------------------------------------------------------------
// Tensor-core flash attention (round-7 version, unchanged).
// ---------------------------------------------------------------------------
#define QSTR 80
#define PSTR 68
#define ATTN_SMEM ((3 * 64 * QSTR + 64 * PSTR) * 4)

__global__ __launch_bounds__(128) void attn_mma(
    const float* __restrict__ qkv, float* __restrict__ O)
{
    extern __shared__ float sm[];
    float* Qs = sm;                    // [64][QSTR] (d permuted)
    float* Ks = Qs + 64 * QSTR;        // [64][QSTR] (d permuted)
    float* VT = Ks + 64 * QSTR;        // [d=64][QSTR] (kv permuted)
    float* Ps = VT + 64 * QSTR;        // [q=64][PSTR] (kv permuted)

    const int qt = blockIdx.x, bh = blockIdx.y;
    const int b = bh >> 4, h = bh & 15;
    const int tid = threadIdx.x, wid = tid >> 5, lane = tid & 31;
    const int gID = lane >> 2, tIG = lane & 3;
    const size_t row_base = (size_t)b * S_;
    const int qoff = h * HD_, koff = H_ + h * HD_, voff = 2 * H_ + h * HD_;

    {
        const int r = tid >> 1, ch = (tid & 1) * 32;
        const float4* src = (const float4*)(qkv + (row_base + qt * 64 + r) * QKV_N + qoff + ch);
        float4* dst = (float4*)(Qs + r * QSTR + ch);
#pragma unroll
        for (int j = 0; j < 8; j++) dst[j] = src[j];
    }
    __syncthreads();

    uint4 qa[4], qb[4];
    const int qrow = wid * 16 + gID;
#pragma unroll
    for (int kb = 0; kb < 4; kb++) {
        qa[kb] = *(const uint4*)(Qs + qrow * QSTR + kb * 16 + tIG * 4);
        qb[kb] = *(const uint4*)(Qs + (qrow + 8) * QSTR + kb * 16 + tIG * 4);
    }

    float m0 = -1e30f, m1 = -1e30f, l0 = 0.f, l1 = 0.f;
    float oacc[8][4];
#pragma unroll
    for (int i = 0; i < 8; i++)
#pragma unroll
        for (int j = 0; j < 4; j++) oacc[i][j] = 0.f;

    const float scale = 0.125f;

    for (int kt = 0; kt < S_ / 64; kt++) {
        __syncthreads();

        {
            const int r = tid >> 1, ch = (tid & 1) * 32;
            const float* gk = qkv + (row_base + kt * 64 + r) * QKV_N + koff + ch;
            const uint32_t sk = smem_u32(Ks + r * QSTR + ch);
#pragma unroll
            for (int j = 0; j < 8; j++) CP_ASYNC16(sk + j * 16, gk + j * 4);
            CP_COMMIT();
        }
        {
            const int kv = tid & 63, half = tid >> 6;
            const float4* gv = (const float4*)(qkv + (row_base + kt * 64 + kv) * QKV_N + voff + half * 32);
            const int pk = pj(kv);
#pragma unroll
            for (int j = 0; j < 8; j++) {
                const float4 v = gv[j];
                const int d = half * 32 + j * 4;
                VT[(d + 0) * QSTR + pk] = v.x;
                VT[(d + 1) * QSTR + pk] = v.y;
                VT[(d + 2) * QSTR + pk] = v.z;
                VT[(d + 3) * QSTR + pk] = v.w;
            }
        }
        asm volatile("cp.async.wait_group 0;" ::: "memory");
        __syncthreads();

        float sacc[8][4];
#pragma unroll
        for (int i = 0; i < 8; i++)
#pragma unroll
            for (int j = 0; j < 4; j++) sacc[i][j] = 0.f;

#pragma unroll
        for (int kb = 0; kb < 4; kb++) {
            const uint32_t aa0[4] = {qa[kb].x, qb[kb].x, qa[kb].y, qb[kb].y};
            const uint32_t aa1[4] = {qa[kb].z, qb[kb].z, qa[kb].w, qb[kb].w};
#pragma unroll
            for (int nt = 0; nt < 8; nt++) {
                const uint4 kv8 = *(const uint4*)(Ks + (nt * 8 + gID) * QSTR + kb * 16 + tIG * 4);
                const uint32_t bb0[2] = {kv8.x, kv8.y};
                const uint32_t bb1[2] = {kv8.z, kv8.w};
                mma_tf32(sacc[nt], aa0, bb0);
                mma_tf32(sacc[nt], aa1, bb1);
            }
        }

        float mx0 = -1e30f, mx1 = -1e30f;
#pragma unroll
        for (int nt = 0; nt < 8; nt++) {
            mx0 = fmaxf(mx0, fmaxf(sacc[nt][0], sacc[nt][1]));
            mx1 = fmaxf(mx1, fmaxf(sacc[nt][2], sacc[nt][3]));
        }
        mx0 = fmaxf(mx0, __shfl_xor_sync(0xffffffffu, mx0, 1));
        mx0 = fmaxf(mx0, __shfl_xor_sync(0xffffffffu, mx0, 2));
        mx1 = fmaxf(mx1, __shfl_xor_sync(0xffffffffu, mx1, 1));
        mx1 = fmaxf(mx1, __shfl_xor_sync(0xffffffffu, mx1, 2));

        const float mn0 = fmaxf(m0, mx0 * scale);
        const float mn1 = fmaxf(m1, mx1 * scale);
        const float corr0 = __expf(m0 - mn0);
        const float corr1 = __expf(m1 - mn1);

        float sum0 = 0.f, sum1 = 0.f;
#pragma unroll
        for (int nt = 0; nt < 8; nt++) {
            float p0 = tf32r(__expf(sacc[nt][0] * scale - mn0));
            float p1 = tf32r(__expf(sacc[nt][1] * scale - mn0));
            float p2 = tf32r(__expf(sacc[nt][2] * scale - mn1));
            float p3 = tf32r(__expf(sacc[nt][3] * scale - mn1));
            sum0 += p0 + p1; sum1 += p2 + p3;
            sacc[nt][0] = p0; sacc[nt][1] = p1; sacc[nt][2] = p2; sacc[nt][3] = p3;
        }
        sum0 += __shfl_xor_sync(0xffffffffu, sum0, 1);
        sum0 += __shfl_xor_sync(0xffffffffu, sum0, 2);
        sum1 += __shfl_xor_sync(0xffffffffu, sum1, 1);
        sum1 += __shfl_xor_sync(0xffffffffu, sum1, 2);

        l0 = l0 * corr0 + sum0; m0 = mn0;
        l1 = l1 * corr1 + sum1; m1 = mn1;
#pragma unroll
        for (int nt = 0; nt < 8; nt++) {
            oacc[nt][0] *= corr0; oacc[nt][1] *= corr0;
            oacc[nt][2] *= corr1; oacc[nt][3] *= corr1;
        }

#pragma unroll
        for (int nt = 0; nt < 8; nt++) {
            const int c = nt * 8 + tIG * 2;
            const int pc0 = pj(c), pc1 = pj(c + 1);
            Ps[qrow * PSTR + pc0]       = sacc[nt][0];
            Ps[qrow * PSTR + pc1]       = sacc[nt][1];
            Ps[(qrow + 8) * PSTR + pc0] = sacc[nt][2];
            Ps[(qrow + 8) * PSTR + pc1] = sacc[nt][3];
        }
        __syncwarp();

#pragma unroll
        for (int kb = 0; kb < 4; kb++) {
            const uint4 pa = *(const uint4*)(Ps + qrow * PSTR + kb * 16 + tIG * 4);
            const uint4 pb = *(const uint4*)(Ps + (qrow + 8) * PSTR + kb * 16 + tIG * 4);
            const uint32_t aa0[4] = {pa.x, pb.x, pa.y, pb.y};
            const uint32_t aa1[4] = {pa.z, pb.z, pa.w, pb.w};
#pragma unroll
            for (int nt = 0; nt < 8; nt++) {
                const uint4 vv = *(const uint4*)(VT + (nt * 8 + gID) * QSTR + kb * 16 + tIG * 4);
                const uint32_t bb0[2] = {vv.x, vv.y};
                const uint32_t bb1[2] = {vv.z, vv.w};
                mma_tf32(oacc[nt], aa0, bb0);
                mma_tf32(oacc[nt], aa1, bb1);
            }
        }
    }

    const float il0 = 1.f / l0, il1 = 1.f / l1;
    float* orow0 = O + (row_base + qt * 64 + qrow) * H_;
    float* orow1 = O + (row_base + qt * 64 + qrow + 8) * H_;
#pragma unroll
    for (int nt = 0; nt < 8; nt++) {
        const int c = h * HD_ + nt * 8 + tIG * 2;
        const int pc0 = pj(c), pc1 = pj(c + 1);
        orow0[pc0] = tf32r(oacc[nt][0] * il0);
        orow0[pc1] = tf32r(oacc[nt][1] * il0);
        orow1[pc0] = tf32r(oacc[nt][2] * il1);
        orow1[pc1] = tf32r(oacc[nt][3] * il1);
    }
}

// ---------------------------------------------------------------------------
// Launch
// ---------------------------------------------------------------------------
extern "C" void kernel_launch(void* const* d_in, const int* in_sizes, int n_in,
                              void* d_out, int out_size)
{
    const float* x     = (const float*)d_in[0];
    const float* ln1_w = (const float*)d_in[1];
    const float* ln1_b = (const float*)d_in[2];
    const float* Wqkv  = (const float*)d_in[3];
    const float* bqkv  = (const float*)d_in[4];
    const float* Wo    = (const float*)d_in[5];
    const float* bo    = (const float*)d_in[6];
    const float* ln2_w = (const float*)d_in[7];
    const float* ln2_b = (const float*)d_in[8];
    const float* fc1_w = (const float*)d_in[9];
    const float* fc1_b = (const float*)d_in[10];
    const float* fc2_w = (const float*)d_in[11];
    const float* fc2_b = (const float*)d_in[12];
    float* out = (float*)d_out;

    float *h, *qkv, *o, *x2, *h2, *a, *wqkvT, *woT, *w1T, *w2T;
    cudaGetSymbolAddress((void**)&h,   g_h);
    cudaGetSymbolAddress((void**)&qkv, g_qkv);
    cudaGetSymbolAddress((void**)&o,   g_o);
    cudaGetSymbolAddress((void**)&x2,  g_x2);
    cudaGetSymbolAddress((void**)&h2,  g_h2);
    cudaGetSymbolAddress((void**)&a,   g_a);
    cudaGetSymbolAddress((void**)&wqkvT, g_wqkvT);
    cudaGetSymbolAddress((void**)&woT,   g_woT);
    cudaGetSymbolAddress((void**)&w1T,   g_w1T);
    cudaGetSymbolAddress((void**)&w2T,   g_w2T);

    cudaFuncSetAttribute(attn_mma,
                         cudaFuncAttributeMaxDynamicSharedMemorySize, ATTN_SMEM);
    cudaFuncSetAttribute(gemm_mma,
                         cudaFuncAttributeMaxDynamicSharedMemorySize, GEMM_SMEM);

    // 0) weight prepass: transpose + tf32-round + k-permute
    wtrans<<<dim3(QKV_N / 32, H_ / 32), 256>>>(Wqkv, wqkvT, H_, QKV_N);
    wtrans<<<dim3(H_ / 32,    H_ / 32), 256>>>(Wo,   woT,   H_, H_);
    wtrans<<<dim3(E_ / 32,    H_ / 32), 256>>>(fc1_w, w1T,  H_, E_);
    wtrans<<<dim3(H_ / 32,    E_ / 32), 256>>>(fc2_w, w2T,  E_, H_);

    // 1) LN1 (perm+tf32 out)
    ln_kernel<<<M_, 256>>>(x, ln1_w, ln1_b, h);
    // 2) QKV projection (mode 3: Q,K perm+tf32; V plain tf32)
    gemm_mma<<<dim3(QKV_N / 128, M_ / 128), 128, GEMM_SMEM>>>(
        h, wqkvT, bqkv, nullptr, qkv, M_, QKV_N, H_, 3);
    // 3) attention (tensor cores; perm+tf32 out)
    attn_mma<<<dim3(S_ / 64, B_ * NH_), 128, ATTN_SMEM>>>(qkv, o);
    // 4) Wo + residual
    gemm_mma<<<dim3(H_ / 128, M_ / 128), 128, GEMM_SMEM>>>(
        o, woT, bo, x, x2, M_, H_, H_, 1);
    // 5) LN2 (perm+tf32 out)
    ln_kernel<<<M_, 256>>>(x2, ln2_w, ln2_b, h2);
    // 6) FC1 + GELU (perm+tf32 out)
    gemm_mma<<<dim3(E_ / 128, M_ / 128), 128, GEMM_SMEM>>>(
        h2, w1T, fc1_b, nullptr, a, M_, E_, H_, 2);
    // 7) FC2 + residual -> out
    gemm_mma<<<dim3(H_ / 128, M_ / 128), 128, GEMM_SMEM>>>(
        a, w2T, fc2_b, x2, out, M_, H_, E_, 1);
}

// round 11
// speedup vs baseline: 1.3099x; 1.3099x over previous
#include <cuda_runtime.h>
#include <cuda_fp16.h>
#include <cstdint>
#include <math.h>

// ---------------------------------------------------------------------------
// Problem constants
// ---------------------------------------------------------------------------
#define B_   4
#define S_   2048
#define H_   1024
#define NH_  16
#define HD_  64
#define E_   4096
#define M_   (B_ * S_)          // 8192 tokens
#define QKV_N (3 * H_)          // 3072

// ---------------------------------------------------------------------------
// Scratch (device globals — no allocation allowed)
// ---------------------------------------------------------------------------
__device__ __half g_h  [M_ * H_];     // ln1 output (fp16, ph-perm)
__device__ float  g_qkv[M_ * QKV_N];  // qkv: Q,K fp32 pj-perm; V plain tf32
__device__ __half g_o  [M_ * H_];     // attention output (fp16, ph-perm)
__device__ float  g_x2 [M_ * H_];     // x + attn@Wo + bo (plain fp32)
__device__ __half g_h2 [M_ * H_];     // ln2 output (fp16, ph-perm)
__device__ __half g_a  [M_ * E_];     // gelu(fc1) (fp16, ph-perm)
// transposed fp16 weights: [N][K], ph-permuted
__device__ __half g_wqkvT[QKV_N * H_];
__device__ __half g_woT  [H_ * H_];
__device__ __half g_w1T  [E_ * H_];
__device__ __half g_w2T  [H_ * E_];

// ---------------------------------------------------------------------------
// Helpers
// ---------------------------------------------------------------------------
__device__ __forceinline__ uint32_t smem_u32(const void* p) {
    uint32_t a;
    asm("{ .reg .u64 t; cvta.to.shared.u64 t, %1; cvt.u32.u64 %0, t; }"
        : "=r"(a) : "l"(p));
    return a;
}
// tf32 round-to-nearest (rna); result returned as float bits (attention path)
__device__ __forceinline__ float tf32r(float x) {
    uint32_t r;
    asm("cvt.rna.tf32.f32 %0, %1;" : "=r"(r) : "f"(x));
    return __uint_as_float(r);
}
// tf32 permutation within 16-blocks (attention fp32 path)
__device__ __forceinline__ int pj(int k) {
    return (k & ~15) | ((k & 3) << 2) | ((k >> 2) & 3);
}
// fp16 permutation within 32-blocks: thread tIG's halves {2t,2t+1,2t+8,2t+9}
// of both k16 sub-blocks land contiguously in its 16B LDS.128 slice.
__device__ __forceinline__ int ph(int k) {
    const int kk  = k & 15;
    const int blk = (k >> 4) & 1;
    const int o   = kk & 1;
    const int g   = (kk >> 1) & 3;
    const int w   = ((kk >> 3) << 1) | o;
    return (k & ~31) | (g * 8 + blk * 4 + w);
}

__device__ __forceinline__ void mma_f16(float* c, const uint32_t* a, const uint32_t* b) {
    asm volatile(
        "mma.sync.aligned.m16n8k16.row.col.f32.f16.f16.f32 "
        "{%0,%1,%2,%3}, {%4,%5,%6,%7}, {%8,%9}, {%0,%1,%2,%3};"
        : "+f"(c[0]), "+f"(c[1]), "+f"(c[2]), "+f"(c[3])
        : "r"(a[0]), "r"(a[1]), "r"(a[2]), "r"(a[3]), "r"(b[0]), "r"(b[1]));
}
__device__ __forceinline__ void mma_tf32(float* c, const uint32_t* a, const uint32_t* b) {
    asm volatile(
        "mma.sync.aligned.m16n8k8.row.col.f32.tf32.tf32.f32 "
        "{%0,%1,%2,%3}, {%4,%5,%6,%7}, {%8,%9}, {%0,%1,%2,%3};"
        : "+f"(c[0]), "+f"(c[1]), "+f"(c[2]), "+f"(c[3])
        : "r"(a[0]), "r"(a[1]), "r"(a[2]), "r"(a[3]), "r"(b[0]), "r"(b[1]));
}

#define CP_ASYNC16(saddr, gptr) \
    asm volatile("cp.async.cg.shared.global [%0], [%1], 16;" \
        :: "r"(saddr), "l"(gptr) : "memory")
#define CP_COMMIT() asm volatile("cp.async.commit_group;" ::: "memory")

// ---------------------------------------------------------------------------
// Weight transpose + fp16-round + ph-permute:  W[K][N] fp32 -> WT[N][K] fp16
// ---------------------------------------------------------------------------
__global__ __launch_bounds__(256) void wtrans(
    const float* __restrict__ W, __half* __restrict__ WT, int K, int N)
{
    __shared__ float t[32][33];
    const int n0 = blockIdx.x * 32, k0 = blockIdx.y * 32;
    const int tx = threadIdx.x & 31, ty = threadIdx.x >> 5;
#pragma unroll
    for (int r = 0; r < 4; r++)
        t[ty + 8 * r][tx] = W[(size_t)(k0 + ty + 8 * r) * N + n0 + tx];
    __syncthreads();
#pragma unroll
    for (int r = 0; r < 4; r++) {
        const int n = n0 + ty + 8 * r;
        const int k = k0 + tx;
        WT[(size_t)n * K + ph(k)] = __float2half_rn(t[tx][ty + 8 * r]);
    }
}

// ---------------------------------------------------------------------------
// FP16 tensor-core GEMM: C = A @ B + bias (+res/gelu). A [M][K] fp16 ph-perm,
// BT [N][K] fp16 ph-perm. 128x128 CTA, BK=64, 256 threads, 8 warps (2m x 4n),
// warp tile 64x32, m16n8k16, 3-stage cp.async (32KB/stage), 2 CTAs/SM.
// Row stride 128B with 64B parity XOR swizzle (conflict-free LDS.128).
// mode 1: bias+residual -> C fp32; mode 2: bias+GELU -> Ch fp16 ph-perm;
// mode 3: bias -> C fp32 QKV layout (cols<2048 pj-perm tf32, else plain tf32)
// ---------------------------------------------------------------------------
#define STAGE_BYTES 32768                // A 16KB + B 16KB
#define GEMM_SMEM   (3 * STAGE_BYTES)    // 98304 per CTA

__global__ __launch_bounds__(256, 2) void gemm_mma(
    const __half* __restrict__ A, const __half* __restrict__ BT,
    const float* __restrict__ bias, const float* __restrict__ R,
    float* __restrict__ C, __half* __restrict__ Ch,
    int M, int N, int K, int mode)
{
    extern __shared__ char smem[];
    const int tid = threadIdx.x;
    const int wid = tid >> 5, lane = tid & 31;
    const int gID = lane >> 2, tIG = lane & 3;
    const int warp_m = wid & 1, warp_n = wid >> 1;   // 2 x 4
    const int brow = blockIdx.y * 128, bcol = blockIdx.x * 128;
    const uint32_t sb = smem_u32(smem);

    // loader: row = tid>>1 (0..127), seg = tid&1 (64B half of the 128B row)
    const int lrow = tid >> 1;
    const int lseg = tid & 1;
    const __half* Ag = A  + (size_t)(brow + lrow) * K + lseg * 32;
    const __half* Bg = BT + (size_t)(bcol + lrow) * K + lseg * 32;
    const uint32_t aoff = (uint32_t)(lrow * 128 + ((lseg ^ (lrow & 1)) << 6));
    const uint32_t boff = aoff + 16384;

    float acc[4][4][4];
#pragma unroll
    for (int i = 0; i < 4; i++)
#pragma unroll
        for (int j = 0; j < 4; j++)
#pragma unroll
            for (int t = 0; t < 4; t++) acc[i][j][t] = 0.f;

    const int nt_tiles = K >> 6;

    auto issue = [&](int kt) {
        const uint32_t st = sb + (uint32_t)(kt % 3) * STAGE_BYTES;
        const __half* ga = Ag + kt * 64;
        const __half* gb = Bg + kt * 64;
#pragma unroll
        for (int i = 0; i < 4; i++) {
            CP_ASYNC16(st + aoff + i * 16, ga + i * 8);
            CP_ASYNC16(st + boff + i * 16, gb + i * 8);
        }
        CP_COMMIT();
    };

    issue(0); issue(1);

    const int m_base = warp_m * 64;
    const int n_base = warp_n * 32;

    for (int kt = 0; kt < nt_tiles; kt++) {
        if (kt + 1 < nt_tiles) asm volatile("cp.async.wait_group 1;" ::: "memory");
        else                   asm volatile("cp.async.wait_group 0;" ::: "memory");
        __syncthreads();
        if (kt + 2 < nt_tiles) issue(kt + 2);

        const char* stage = smem + (size_t)(kt % 3) * STAGE_BYTES;
        const uint32_t* as = (const uint32_t*)stage;         // rows: 32 u32 each
        const uint32_t* bs = as + 4096;                      // +16KB

#pragma unroll
        for (int c = 0; c < 2; c++) {
            uint4 alow[4], ahigh[4], bv[4];
#pragma unroll
            for (int mt = 0; mt < 4; mt++) {
                const int r0 = m_base + mt * 16 + gID;
                const uint32_t* p = as + r0 * 32 + ((c ^ (r0 & 1)) << 4) + tIG * 4;
                alow[mt]  = *(const uint4*)p;
                ahigh[mt] = *(const uint4*)(p + 256);   // row r0+8 (same parity)
            }
#pragma unroll
            for (int nt = 0; nt < 4; nt++) {
                const int rB = n_base + nt * 8 + gID;
                bv[nt] = *(const uint4*)(bs + rB * 32 + ((c ^ (rB & 1)) << 4) + tIG * 4);
            }
#pragma unroll
            for (int mt = 0; mt < 4; mt++) {
                const uint32_t aa0[4] = {alow[mt].x, ahigh[mt].x, alow[mt].y, ahigh[mt].y};
                const uint32_t aa1[4] = {alow[mt].z, ahigh[mt].z, alow[mt].w, ahigh[mt].w};
#pragma unroll
                for (int nt = 0; nt < 4; nt++) {
                    const uint32_t bb0[2] = {bv[nt].x, bv[nt].y};
                    const uint32_t bb1[2] = {bv[nt].z, bv[nt].w};
                    mma_f16(acc[mt][nt], aa0, bb0);
                    mma_f16(acc[mt][nt], aa1, bb1);
                }
            }
        }
    }

    // --- epilogue ---
#pragma unroll
    for (int mt = 0; mt < 4; mt++) {
#pragma unroll
        for (int half_ = 0; half_ < 2; half_++) {
            const int row = brow + m_base + mt * 16 + gID + half_ * 8;
            float* crow = C + (size_t)row * N;
            const float* rrow = (mode == 1) ? (R + (size_t)row * N) : nullptr;
#pragma unroll
            for (int nt = 0; nt < 4; nt++) {
                const int col = bcol + n_base + nt * 8 + tIG * 2;
                float v0 = acc[mt][nt][half_ * 2 + 0];
                float v1 = acc[mt][nt][half_ * 2 + 1];
                const float2 bb = *(const float2*)(bias + col);
                v0 += bb.x; v1 += bb.y;
                if (mode == 1) {
                    const float2 rr = *(const float2*)(rrow + col);
                    v0 += rr.x; v1 += rr.y;
                    *(float2*)(crow + col) = make_float2(v0, v1);
                } else if (mode == 2) {
                    v0 = 0.5f * v0 * (1.f + erff(v0 * 0.70710678118654752f));
                    v1 = 0.5f * v1 * (1.f + erff(v1 * 0.70710678118654752f));
                    *(__half2*)(Ch + (size_t)row * N + ph(col)) =
                        __floats2half2_rn(v0, v1);
                } else { // mode 3: QKV layout (fp32 for attention)
                    if (col < 2 * H_) {
                        crow[pj(col)]     = tf32r(v0);
                        crow[pj(col + 1)] = tf32r(v1);
                    } else {
                        *(float2*)(crow + col) = make_float2(tf32r(v0), tf32r(v1));
                    }
                }
            }
        }
    }
}

// ---------------------------------------------------------------------------
// LayerNorm: one block per row of 1024; output fp16, ph-permuted
// ---------------------------------------------------------------------------
__global__ __launch_bounds__(256) void ln_kernel(
    const float* __restrict__ x, const float* __restrict__ w,
    const float* __restrict__ b, __half* __restrict__ out)
{
    const int row = blockIdx.x;
    const int tid = threadIdx.x;
    const float* xr = x + (size_t)row * H_;

    float v[4];
    float s = 0.f, s2 = 0.f;
#pragma unroll
    for (int i = 0; i < 4; i++) {
        v[i] = xr[tid + 256 * i];
        s += v[i];
        s2 += v[i] * v[i];
    }
#pragma unroll
    for (int off = 16; off > 0; off >>= 1) {
        s  += __shfl_xor_sync(0xffffffffu, s,  off);
        s2 += __shfl_xor_sync(0xffffffffu, s2, off);
    }
    __shared__ float red[8], red2[8];
    const int wid = tid >> 5, lane = tid & 31;
    if (lane == 0) { red[wid] = s; red2[wid] = s2; }
    __syncthreads();
    if (tid < 32) {
        float a = (tid < 8) ? red[tid]  : 0.f;
        float c = (tid < 8) ? red2[tid] : 0.f;
#pragma unroll
        for (int off = 4; off > 0; off >>= 1) {
            a += __shfl_xor_sync(0xffffffffu, a, off);
            c += __shfl_xor_sync(0xffffffffu, c, off);
        }
        if (tid == 0) { red[0] = a; red2[0] = c; }
    }
    __syncthreads();
    const float mu  = red[0] * (1.f / H_);
    const float var = red2[0] * (1.f / H_) - mu * mu;
    const float rstd = rsqrtf(var + 1e-5f);

    __half* orow = out + (size_t)row * H_;
#pragma unroll
    for (int i = 0; i < 4; i++) {
        const int c = tid + 256 * i;
        orow[ph(c)] = __float2half_rn((v[i] - mu) * rstd * w[c] + b[c]);
    }
}

// ---------------------------------------------------------------------------
// Tensor-core flash attention (tf32 QK^T / PV, round-7 structure).
// Output now fp16 ph-permuted (feeds Wo fp16 GEMM).
// ---------------------------------------------------------------------------
#define QSTR 80
#define PSTR 68
#define ATTN_SMEM ((3 * 64 * QSTR + 64 * PSTR) * 4)

__global__ __launch_bounds__(128) void attn_mma(
    const float* __restrict__ qkv, __half* __restrict__ O)
{
    extern __shared__ float sm[];
    float* Qs = sm;                    // [64][QSTR] (d permuted)
    float* Ks = Qs + 64 * QSTR;        // [64][QSTR] (d permuted)
    float* VT = Ks + 64 * QSTR;        // [d=64][QSTR] (kv permuted)
    float* Ps = VT + 64 * QSTR;        // [q=64][PSTR] (kv permuted)

    const int qt = blockIdx.x, bh = blockIdx.y;
    const int b = bh >> 4, h = bh & 15;
    const int tid = threadIdx.x, wid = tid >> 5, lane = tid & 31;
    const int gID = lane >> 2, tIG = lane & 3;
    const size_t row_base = (size_t)b * S_;
    const int qoff = h * HD_, koff = H_ + h * HD_, voff = 2 * H_ + h * HD_;

    {
        const int r = tid >> 1, ch = (tid & 1) * 32;
        const float4* src = (const float4*)(qkv + (row_base + qt * 64 + r) * QKV_N + qoff + ch);
        float4* dst = (float4*)(Qs + r * QSTR + ch);
#pragma unroll
        for (int j = 0; j < 8; j++) dst[j] = src[j];
    }
    __syncthreads();

    uint4 qa[4], qb[4];
    const int qrow = wid * 16 + gID;
#pragma unroll
    for (int kb = 0; kb < 4; kb++) {
        qa[kb] = *(const uint4*)(Qs + qrow * QSTR + kb * 16 + tIG * 4);
        qb[kb] = *(const uint4*)(Qs + (qrow + 8) * QSTR + kb * 16 + tIG * 4);
    }

    float m0 = -1e30f, m1 = -1e30f, l0 = 0.f, l1 = 0.f;
    float oacc[8][4];
#pragma unroll
    for (int i = 0; i < 8; i++)
#pragma unroll
        for (int j = 0; j < 4; j++) oacc[i][j] = 0.f;

    const float scale = 0.125f;

    for (int kt = 0; kt < S_ / 64; kt++) {
        __syncthreads();

        {
            const int r = tid >> 1, ch = (tid & 1) * 32;
            const float* gk = qkv + (row_base + kt * 64 + r) * QKV_N + koff + ch;
            const uint32_t sk = smem_u32(Ks + r * QSTR + ch);
#pragma unroll
            for (int j = 0; j < 8; j++) CP_ASYNC16(sk + j * 16, gk + j * 4);
            CP_COMMIT();
        }
        {
            const int kv = tid & 63, half_ = tid >> 6;
            const float4* gv = (const float4*)(qkv + (row_base + kt * 64 + kv) * QKV_N + voff + half_ * 32);
            const int pk = pj(kv);
#pragma unroll
            for (int j = 0; j < 8; j++) {
                const float4 v = gv[j];
                const int d = half_ * 32 + j * 4;
                VT[(d + 0) * QSTR + pk] = v.x;
                VT[(d + 1) * QSTR + pk] = v.y;
                VT[(d + 2) * QSTR + pk] = v.z;
                VT[(d + 3) * QSTR + pk] = v.w;
            }
        }
        asm volatile("cp.async.wait_group 0;" ::: "memory");
        __syncthreads();

        float sacc[8][4];
#pragma unroll
        for (int i = 0; i < 8; i++)
#pragma unroll
            for (int j = 0; j < 4; j++) sacc[i][j] = 0.f;

#pragma unroll
        for (int kb = 0; kb < 4; kb++) {
            const uint32_t aa0[4] = {qa[kb].x, qb[kb].x, qa[kb].y, qb[kb].y};
            const uint32_t aa1[4] = {qa[kb].z, qb[kb].z, qa[kb].w, qb[kb].w};
#pragma unroll
            for (int nt = 0; nt < 8; nt++) {
                const uint4 kv8 = *(const uint4*)(Ks + (nt * 8 + gID) * QSTR + kb * 16 + tIG * 4);
                const uint32_t bb0[2] = {kv8.x, kv8.y};
                const uint32_t bb1[2] = {kv8.z, kv8.w};
                mma_tf32(sacc[nt], aa0, bb0);
                mma_tf32(sacc[nt], aa1, bb1);
            }
        }

        float mx0 = -1e30f, mx1 = -1e30f;
#pragma unroll
        for (int nt = 0; nt < 8; nt++) {
            mx0 = fmaxf(mx0, fmaxf(sacc[nt][0], sacc[nt][1]));
            mx1 = fmaxf(mx1, fmaxf(sacc[nt][2], sacc[nt][3]));
        }
        mx0 = fmaxf(mx0, __shfl_xor_sync(0xffffffffu, mx0, 1));
        mx0 = fmaxf(mx0, __shfl_xor_sync(0xffffffffu, mx0, 2));
        mx1 = fmaxf(mx1, __shfl_xor_sync(0xffffffffu, mx1, 1));
        mx1 = fmaxf(mx1, __shfl_xor_sync(0xffffffffu, mx1, 2));

        const float mn0 = fmaxf(m0, mx0 * scale);
        const float mn1 = fmaxf(m1, mx1 * scale);
        const float corr0 = __expf(m0 - mn0);
        const float corr1 = __expf(m1 - mn1);

        float sum0 = 0.f, sum1 = 0.f;
#pragma unroll
        for (int nt = 0; nt < 8; nt++) {
            float p0 = tf32r(__expf(sacc[nt][0] * scale - mn0));
            float p1 = tf32r(__expf(sacc[nt][1] * scale - mn0));
            float p2 = tf32r(__expf(sacc[nt][2] * scale - mn1));
            float p3 = tf32r(__expf(sacc[nt][3] * scale - mn1));
            sum0 += p0 + p1; sum1 += p2 + p3;
            sacc[nt][0] = p0; sacc[nt][1] = p1; sacc[nt][2] = p2; sacc[nt][3] = p3;
        }
        sum0 += __shfl_xor_sync(0xffffffffu, sum0, 1);
        sum0 += __shfl_xor_sync(0xffffffffu, sum0, 2);
        sum1 += __shfl_xor_sync(0xffffffffu, sum1, 1);
        sum1 += __shfl_xor_sync(0xffffffffu, sum1, 2);

        l0 = l0 * corr0 + sum0; m0 = mn0;
        l1 = l1 * corr1 + sum1; m1 = mn1;
#pragma unroll
        for (int nt = 0; nt < 8; nt++) {
            oacc[nt][0] *= corr0; oacc[nt][1] *= corr0;
            oacc[nt][2] *= corr1; oacc[nt][3] *= corr1;
        }

#pragma unroll
        for (int nt = 0; nt < 8; nt++) {
            const int c = nt * 8 + tIG * 2;
            const int pc0 = pj(c), pc1 = pj(c + 1);
            Ps[qrow * PSTR + pc0]       = sacc[nt][0];
            Ps[qrow * PSTR + pc1]       = sacc[nt][1];
            Ps[(qrow + 8) * PSTR + pc0] = sacc[nt][2];
            Ps[(qrow + 8) * PSTR + pc1] = sacc[nt][3];
        }
        __syncwarp();

#pragma unroll
        for (int kb = 0; kb < 4; kb++) {
            const uint4 pa = *(const uint4*)(Ps + qrow * PSTR + kb * 16 + tIG * 4);
            const uint4 pb = *(const uint4*)(Ps + (qrow + 8) * PSTR + kb * 16 + tIG * 4);
            const uint32_t aa0[4] = {pa.x, pb.x, pa.y, pb.y};
            const uint32_t aa1[4] = {pa.z, pb.z, pa.w, pb.w};
#pragma unroll
            for (int nt = 0; nt < 8; nt++) {
                const uint4 vv = *(const uint4*)(VT + (nt * 8 + gID) * QSTR + kb * 16 + tIG * 4);
                const uint32_t bb0[2] = {vv.x, vv.y};
                const uint32_t bb1[2] = {vv.z, vv.w};
                mma_tf32(oacc[nt], aa0, bb0);
                mma_tf32(oacc[nt], aa1, bb1);
            }
        }
    }

    // --- write O as fp16 ph-permuted (feeds Wo GEMM) ---
    const float il0 = 1.f / l0, il1 = 1.f / l1;
    __half* orow0 = O + (row_base + qt * 64 + qrow) * H_;
    __half* orow1 = O + (row_base + qt * 64 + qrow + 8) * H_;
#pragma unroll
    for (int nt = 0; nt < 8; nt++) {
        const int c = h * HD_ + nt * 8 + tIG * 2;
        const int pc = ph(c);   // ph(c+1) == ph(c)+1 for even c
        *(__half2*)(orow0 + pc) = __floats2half2_rn(oacc[nt][0] * il0, oacc[nt][1] * il0);
        *(__half2*)(orow1 + pc) = __floats2half2_rn(oacc[nt][2] * il1, oacc[nt][3] * il1);
    }
}

// ---------------------------------------------------------------------------
// Launch
// ---------------------------------------------------------------------------
extern "C" void kernel_launch(void* const* d_in, const int* in_sizes, int n_in,
                              void* d_out, int out_size)
{
    const float* x     = (const float*)d_in[0];
    const float* ln1_w = (const float*)d_in[1];
    const float* ln1_b = (const float*)d_in[2];
    const float* Wqkv  = (const float*)d_in[3];
    const float* bqkv  = (const float*)d_in[4];
    const float* Wo    = (const float*)d_in[5];
    const float* bo    = (const float*)d_in[6];
    const float* ln2_w = (const float*)d_in[7];
    const float* ln2_b = (const float*)d_in[8];
    const float* fc1_w = (const float*)d_in[9];
    const float* fc1_b = (const float*)d_in[10];
    const float* fc2_w = (const float*)d_in[11];
    const float* fc2_b = (const float*)d_in[12];
    float* out = (float*)d_out;

    __half *h, *o, *h2, *a, *wqkvT, *woT, *w1T, *w2T;
    float *qkv, *x2;
    cudaGetSymbolAddress((void**)&h,   g_h);
    cudaGetSymbolAddress((void**)&qkv, g_qkv);
    cudaGetSymbolAddress((void**)&o,   g_o);
    cudaGetSymbolAddress((void**)&x2,  g_x2);
    cudaGetSymbolAddress((void**)&h2,  g_h2);
    cudaGetSymbolAddress((void**)&a,   g_a);
    cudaGetSymbolAddress((void**)&wqkvT, g_wqkvT);
    cudaGetSymbolAddress((void**)&woT,   g_woT);
    cudaGetSymbolAddress((void**)&w1T,   g_w1T);
    cudaGetSymbolAddress((void**)&w2T,   g_w2T);

    cudaFuncSetAttribute(attn_mma,
                         cudaFuncAttributeMaxDynamicSharedMemorySize, ATTN_SMEM);
    cudaFuncSetAttribute(gemm_mma,
                         cudaFuncAttributeMaxDynamicSharedMemorySize, GEMM_SMEM);

    // 0) weight prepass: transpose + fp16 + ph-permute
    wtrans<<<dim3(QKV_N / 32, H_ / 32), 256>>>(Wqkv, wqkvT, H_, QKV_N);
    wtrans<<<dim3(H_ / 32,    H_ / 32), 256>>>(Wo,   woT,   H_, H_);
    wtrans<<<dim3(E_ / 32,    H_ / 32), 256>>>(fc1_w, w1T,  H_, E_);
    wtrans<<<dim3(H_ / 32,    E_ / 32), 256>>>(fc2_w, w2T,  E_, H_);

    // 1) LN1 (fp16 ph out)
    ln_kernel<<<M_, 256>>>(x, ln1_w, ln1_b, h);
    // 2) QKV projection (mode 3: Q,K fp32 pj; V plain tf32)
    gemm_mma<<<dim3(QKV_N / 128, M_ / 128), 256, GEMM_SMEM>>>(
        h, wqkvT, bqkv, nullptr, qkv, nullptr, M_, QKV_N, H_, 3);
    // 3) attention (tf32 tensor cores; fp16 ph out)
    attn_mma<<<dim3(S_ / 64, B_ * NH_), 128, ATTN_SMEM>>>(qkv, o);
    // 4) Wo + residual (fp32 out)
    gemm_mma<<<dim3(H_ / 128, M_ / 128), 256, GEMM_SMEM>>>(
        o, woT, bo, x, x2, nullptr, M_, H_, H_, 1);
    // 5) LN2 (fp16 ph out)
    ln_kernel<<<M_, 256>>>(x2, ln2_w, ln2_b, h2);
    // 6) FC1 + GELU (fp16 ph out)
    gemm_mma<<<dim3(E_ / 128, M_ / 128), 256, GEMM_SMEM>>>(
        h2, w1T, fc1_b, nullptr, nullptr, a, M_, E_, H_, 2);
    // 7) FC2 + residual -> out (fp32)
    gemm_mma<<<dim3(H_ / 128, M_ / 128), 256, GEMM_SMEM>>>(
        a, w2T, fc2_b, x2, out, nullptr, M_, H_, E_, 1);
}

// round 12
// speedup vs baseline: 1.8023x; 1.3760x over previous
#include <cuda_runtime.h>
#include <cuda_fp16.h>
#include <cstdint>
#include <math.h>

// ---------------------------------------------------------------------------
// Problem constants
// ---------------------------------------------------------------------------
#define B_   4
#define S_   2048
#define H_   1024
#define NH_  16
#define HD_  64
#define E_   4096
#define M_   (B_ * S_)          // 8192 tokens
#define QKV_N (3 * H_)          // 3072

// ---------------------------------------------------------------------------
// Scratch (device globals — no allocation allowed)
// ---------------------------------------------------------------------------
__device__ __half g_h  [M_ * H_];     // ln1 output (fp16, ph-perm)
__device__ __half g_qkv[M_ * QKV_N];  // qkv fp16: Q,K ph-perm; V plain
__device__ __half g_o  [M_ * H_];     // attention output (fp16, ph-perm)
__device__ float  g_x2 [M_ * H_];     // x + attn@Wo + bo (plain fp32)
__device__ __half g_h2 [M_ * H_];     // ln2 output (fp16, ph-perm)
__device__ __half g_a  [M_ * E_];     // gelu(fc1) (fp16, ph-perm)
// transposed fp16 weights: [N][K], ph-permuted
__device__ __half g_wqkvT[QKV_N * H_];
__device__ __half g_woT  [H_ * H_];
__device__ __half g_w1T  [E_ * H_];
__device__ __half g_w2T  [H_ * E_];

// ---------------------------------------------------------------------------
// Helpers
// ---------------------------------------------------------------------------
__device__ __forceinline__ uint32_t smem_u32(const void* p) {
    uint32_t a;
    asm("{ .reg .u64 t; cvta.to.shared.u64 t, %1; cvt.u32.u64 %0, t; }"
        : "=r"(a) : "l"(p));
    return a;
}
// fp16 permutation within 32-blocks: thread tIG's halves {2t,2t+1,2t+8,2t+9}
// of both k16 sub-blocks land contiguously in its 16B LDS.128 slice.
__device__ __forceinline__ int ph(int k) {
    const int kk  = k & 15;
    const int blk = (k >> 4) & 1;
    const int o   = kk & 1;
    const int g   = (kk >> 1) & 3;
    const int w   = ((kk >> 3) << 1) | o;
    return (k & ~31) | (g * 8 + blk * 4 + w);
}
__device__ __forceinline__ float h_round(float x) {
    return __half2float(__float2half_rn(x));
}

__device__ __forceinline__ void mma_f16(float* c, const uint32_t* a, const uint32_t* b) {
    asm volatile(
        "mma.sync.aligned.m16n8k16.row.col.f32.f16.f16.f32 "
        "{%0,%1,%2,%3}, {%4,%5,%6,%7}, {%8,%9}, {%0,%1,%2,%3};"
        : "+f"(c[0]), "+f"(c[1]), "+f"(c[2]), "+f"(c[3])
        : "r"(a[0]), "r"(a[1]), "r"(a[2]), "r"(a[3]), "r"(b[0]), "r"(b[1]));
}

#define CP_ASYNC16(saddr, gptr) \
    asm volatile("cp.async.cg.shared.global [%0], [%1], 16;" \
        :: "r"(saddr), "l"(gptr) : "memory")
#define CP_COMMIT() asm volatile("cp.async.commit_group;" ::: "memory")

// ---------------------------------------------------------------------------
// Weight transpose + fp16-round + ph-permute:  W[K][N] fp32 -> WT[N][K] fp16
// ---------------------------------------------------------------------------
__global__ __launch_bounds__(256) void wtrans(
    const float* __restrict__ W, __half* __restrict__ WT, int K, int N)
{
    __shared__ float t[32][33];
    const int n0 = blockIdx.x * 32, k0 = blockIdx.y * 32;
    const int tx = threadIdx.x & 31, ty = threadIdx.x >> 5;
#pragma unroll
    for (int r = 0; r < 4; r++)
        t[ty + 8 * r][tx] = W[(size_t)(k0 + ty + 8 * r) * N + n0 + tx];
    __syncthreads();
#pragma unroll
    for (int r = 0; r < 4; r++) {
        const int n = n0 + ty + 8 * r;
        const int k = k0 + tx;
        WT[(size_t)n * K + ph(k)] = __float2half_rn(t[tx][ty + 8 * r]);
    }
}

// ---------------------------------------------------------------------------
// FP16 tensor-core GEMM: C = A @ B + bias (+res/gelu). A [M][K] fp16 ph-perm,
// BT [N][K] fp16 ph-perm. 128x128 CTA, BK=64, 256 threads, 8 warps (2m x 4n),
// warp tile 64x32, m16n8k16, 3-stage cp.async (32KB/stage), 2 CTAs/SM.
// Row stride 128B with 64B parity XOR swizzle (conflict-free LDS.128).
// mode 1: bias+residual -> C fp32; mode 2: bias+GELU -> Ch fp16 ph-perm;
// mode 3: bias -> Ch fp16 QKV layout (cols<2048 ph-perm, else plain)
// ---------------------------------------------------------------------------
#define STAGE_BYTES 32768                // A 16KB + B 16KB
#define GEMM_SMEM   (3 * STAGE_BYTES)    // 98304 per CTA

__global__ __launch_bounds__(256, 2) void gemm_mma(
    const __half* __restrict__ A, const __half* __restrict__ BT,
    const float* __restrict__ bias, const float* __restrict__ R,
    float* __restrict__ C, __half* __restrict__ Ch,
    int M, int N, int K, int mode)
{
    extern __shared__ char smem[];
    const int tid = threadIdx.x;
    const int wid = tid >> 5, lane = tid & 31;
    const int gID = lane >> 2, tIG = lane & 3;
    const int warp_m = wid & 1, warp_n = wid >> 1;   // 2 x 4
    const int brow = blockIdx.y * 128, bcol = blockIdx.x * 128;
    const uint32_t sb = smem_u32(smem);

    const int lrow = tid >> 1;
    const int lseg = tid & 1;
    const __half* Ag = A  + (size_t)(brow + lrow) * K + lseg * 32;
    const __half* Bg = BT + (size_t)(bcol + lrow) * K + lseg * 32;
    const uint32_t aoff = (uint32_t)(lrow * 128 + ((lseg ^ (lrow & 1)) << 6));
    const uint32_t boff = aoff + 16384;

    float acc[4][4][4];
#pragma unroll
    for (int i = 0; i < 4; i++)
#pragma unroll
        for (int j = 0; j < 4; j++)
#pragma unroll
            for (int t = 0; t < 4; t++) acc[i][j][t] = 0.f;

    const int nt_tiles = K >> 6;

    auto issue = [&](int kt) {
        const uint32_t st = sb + (uint32_t)(kt % 3) * STAGE_BYTES;
        const __half* ga = Ag + kt * 64;
        const __half* gb = Bg + kt * 64;
#pragma unroll
        for (int i = 0; i < 4; i++) {
            CP_ASYNC16(st + aoff + i * 16, ga + i * 8);
            CP_ASYNC16(st + boff + i * 16, gb + i * 8);
        }
        CP_COMMIT();
    };

    issue(0); issue(1);

    const int m_base = warp_m * 64;
    const int n_base = warp_n * 32;

    for (int kt = 0; kt < nt_tiles; kt++) {
        if (kt + 1 < nt_tiles) asm volatile("cp.async.wait_group 1;" ::: "memory");
        else                   asm volatile("cp.async.wait_group 0;" ::: "memory");
        __syncthreads();
        if (kt + 2 < nt_tiles) issue(kt + 2);

        const char* stage = smem + (size_t)(kt % 3) * STAGE_BYTES;
        const uint32_t* as = (const uint32_t*)stage;
        const uint32_t* bs = as + 4096;

#pragma unroll
        for (int c = 0; c < 2; c++) {
            uint4 alow[4], ahigh[4], bv[4];
#pragma unroll
            for (int mt = 0; mt < 4; mt++) {
                const int r0 = m_base + mt * 16 + gID;
                const uint32_t* p = as + r0 * 32 + ((c ^ (r0 & 1)) << 4) + tIG * 4;
                alow[mt]  = *(const uint4*)p;
                ahigh[mt] = *(const uint4*)(p + 256);
            }
#pragma unroll
            for (int nt = 0; nt < 4; nt++) {
                const int rB = n_base + nt * 8 + gID;
                bv[nt] = *(const uint4*)(bs + rB * 32 + ((c ^ (rB & 1)) << 4) + tIG * 4);
            }
#pragma unroll
            for (int mt = 0; mt < 4; mt++) {
                const uint32_t aa0[4] = {alow[mt].x, ahigh[mt].x, alow[mt].y, ahigh[mt].y};
                const uint32_t aa1[4] = {alow[mt].z, ahigh[mt].z, alow[mt].w, ahigh[mt].w};
#pragma unroll
                for (int nt = 0; nt < 4; nt++) {
                    const uint32_t bb0[2] = {bv[nt].x, bv[nt].y};
                    const uint32_t bb1[2] = {bv[nt].z, bv[nt].w};
                    mma_f16(acc[mt][nt], aa0, bb0);
                    mma_f16(acc[mt][nt], aa1, bb1);
                }
            }
        }
    }

    // --- epilogue ---
#pragma unroll
    for (int mt = 0; mt < 4; mt++) {
#pragma unroll
        for (int half_ = 0; half_ < 2; half_++) {
            const int row = brow + m_base + mt * 16 + gID + half_ * 8;
            float* crow = C + (size_t)row * N;
            const float* rrow = (mode == 1) ? (R + (size_t)row * N) : nullptr;
#pragma unroll
            for (int nt = 0; nt < 4; nt++) {
                const int col = bcol + n_base + nt * 8 + tIG * 2;
                float v0 = acc[mt][nt][half_ * 2 + 0];
                float v1 = acc[mt][nt][half_ * 2 + 1];
                const float2 bb = *(const float2*)(bias + col);
                v0 += bb.x; v1 += bb.y;
                if (mode == 1) {
                    const float2 rr = *(const float2*)(rrow + col);
                    v0 += rr.x; v1 += rr.y;
                    *(float2*)(crow + col) = make_float2(v0, v1);
                } else if (mode == 2) {
                    v0 = 0.5f * v0 * (1.f + erff(v0 * 0.70710678118654752f));
                    v1 = 0.5f * v1 * (1.f + erff(v1 * 0.70710678118654752f));
                    *(__half2*)(Ch + (size_t)row * N + ph(col)) =
                        __floats2half2_rn(v0, v1);
                } else { // mode 3: QKV fp16 layout
                    __half* chrow = Ch + (size_t)row * N;
                    if (col < 2 * H_)
                        *(__half2*)(chrow + ph(col)) = __floats2half2_rn(v0, v1);
                    else
                        *(__half2*)(chrow + col)     = __floats2half2_rn(v0, v1);
                }
            }
        }
    }
}

// ---------------------------------------------------------------------------
// LayerNorm: one block per row of 1024; output fp16, ph-permuted
// ---------------------------------------------------------------------------
__global__ __launch_bounds__(256) void ln_kernel(
    const float* __restrict__ x, const float* __restrict__ w,
    const float* __restrict__ b, __half* __restrict__ out)
{
    const int row = blockIdx.x;
    const int tid = threadIdx.x;
    const float* xr = x + (size_t)row * H_;

    float v[4];
    float s = 0.f, s2 = 0.f;
#pragma unroll
    for (int i = 0; i < 4; i++) {
        v[i] = xr[tid + 256 * i];
        s += v[i];
        s2 += v[i] * v[i];
    }
#pragma unroll
    for (int off = 16; off > 0; off >>= 1) {
        s  += __shfl_xor_sync(0xffffffffu, s,  off);
        s2 += __shfl_xor_sync(0xffffffffu, s2, off);
    }
    __shared__ float red[8], red2[8];
    const int wid = tid >> 5, lane = tid & 31;
    if (lane == 0) { red[wid] = s; red2[wid] = s2; }
    __syncthreads();
    if (tid < 32) {
        float a = (tid < 8) ? red[tid]  : 0.f;
        float c = (tid < 8) ? red2[tid] : 0.f;
#pragma unroll
        for (int off = 4; off > 0; off >>= 1) {
            a += __shfl_xor_sync(0xffffffffu, a, off);
            c += __shfl_xor_sync(0xffffffffu, c, off);
        }
        if (tid == 0) { red[0] = a; red2[0] = c; }
    }
    __syncthreads();
    const float mu  = red[0] * (1.f / H_);
    const float var = red2[0] * (1.f / H_) - mu * mu;
    const float rstd = rsqrtf(var + 1e-5f);

    __half* orow = out + (size_t)row * H_;
#pragma unroll
    for (int i = 0; i < 4; i++) {
        const int c = tid + 256 * i;
        orow[ph(c)] = __float2half_rn((v[i] - mu) * rstd * w[c] + b[c]);
    }
}

// ---------------------------------------------------------------------------
// FP16 tensor-core flash attention. Grid (32 q-tiles, 64 b*h), 128 threads.
// Q/K in gmem fp16 ph-perm; V plain fp16. Smem tiles [64][64] halves,
// 128B rows with 64B parity XOR swizzle (conflict-free LDS.128).
// Output fp16 ph-perm (feeds Wo GEMM).
// ---------------------------------------------------------------------------
#define ATTN_SMEM (4 * 64 * 128)   // Qs,Ks,VT,Ps: 8KB each

__global__ __launch_bounds__(128) void attn_mma(
    const __half* __restrict__ qkv, __half* __restrict__ O)
{
    extern __shared__ char asmem[];
    char* Qs = asmem;            // [64 rows][128B]
    char* Ks = Qs + 8192;
    char* VT = Ks + 8192;        // [d=64 rows][kv 128B]
    char* Ps = VT + 8192;        // [q=64 rows][kv 128B]

    const int qt = blockIdx.x, bh = blockIdx.y;
    const int b = bh >> 4, h = bh & 15;
    const int tid = threadIdx.x, wid = tid >> 5, lane = tid & 31;
    const int gID = lane >> 2, tIG = lane & 3;
    const size_t row_base = (size_t)b * S_;
    const int qoff = h * HD_, koff = H_ + h * HD_, voff = 2 * H_ + h * HD_;

    // --- load Q tile (fp16 ph-perm; apply parity swizzle) ---
    {
        const int r = tid >> 1, seg = tid & 1;
        const float4* src = (const float4*)(qkv + (row_base + qt * 64 + r) * QKV_N + qoff + seg * 32);
        float4* dst = (float4*)(Qs + r * 128 + ((seg ^ (r & 1)) << 6));
#pragma unroll
        for (int j = 0; j < 4; j++) dst[j] = src[j];
    }
    __syncthreads();

    // --- Q fragments (kept in regs for whole kernel) ---
    const int qrow = wid * 16 + gID;
    uint4 qa[2], qb[2];
#pragma unroll
    for (int c = 0; c < 2; c++) {
        qa[c] = *(const uint4*)(Qs + qrow * 128       + ((c ^ (qrow & 1)) << 6) + tIG * 16);
        qb[c] = *(const uint4*)(Qs + (qrow + 8) * 128 + ((c ^ (qrow & 1)) << 6) + tIG * 16);
    }

    float m0 = -1e30f, m1 = -1e30f, l0 = 0.f, l1 = 0.f;
    float oacc[8][4];
#pragma unroll
    for (int i = 0; i < 8; i++)
#pragma unroll
        for (int j = 0; j < 4; j++) oacc[i][j] = 0.f;

    const float scale = 0.125f;

    for (int kt = 0; kt < S_ / 64; kt++) {
        __syncthreads();

        // K tile via cp.async (ph-perm copy with swizzle)
        {
            const int r = tid >> 1, seg = tid & 1;
            const __half* gk = qkv + (row_base + kt * 64 + r) * QKV_N + koff + seg * 32;
            const uint32_t sk = smem_u32(Ks) + r * 128 + ((seg ^ (r & 1)) << 6);
#pragma unroll
            for (int j = 0; j < 4; j++) CP_ASYNC16(sk + j * 16, gk + j * 8);
            CP_COMMIT();
        }
        // V transpose: VT[d][ph(kv)] with per-d-row parity swizzle
        {
            const int kv = tid & 63, dh = tid >> 6;
            const __half* gv = qkv + (row_base + kt * 64 + kv) * QKV_N + voff + dh * 32;
            const int kvblk = kv >> 5;
            const int phk = ph(kv) & 31;
#pragma unroll
            for (int j = 0; j < 4; j++) {
                const uint4 vv = *(const uint4*)(gv + j * 8);
                const uint32_t wv[4] = {vv.x, vv.y, vv.z, vv.w};
#pragma unroll
                for (int t = 0; t < 4; t++) {
                    const int d0 = dh * 32 + j * 8 + t * 2;
                    *(__half*)(VT + d0 * 128 + ((kvblk ^ (d0 & 1)) << 6) + phk * 2) =
                        __ushort_as_half((unsigned short)(wv[t] & 0xffff));
                    const int d1 = d0 + 1;
                    *(__half*)(VT + d1 * 128 + ((kvblk ^ (d1 & 1)) << 6) + phk * 2) =
                        __ushort_as_half((unsigned short)(wv[t] >> 16));
                }
            }
        }
        asm volatile("cp.async.wait_group 0;" ::: "memory");
        __syncthreads();

        // --- S = Q @ K^T ---
        float sacc[8][4];
#pragma unroll
        for (int i = 0; i < 8; i++)
#pragma unroll
            for (int j = 0; j < 4; j++) sacc[i][j] = 0.f;

#pragma unroll
        for (int c = 0; c < 2; c++) {
            const uint32_t aa0[4] = {qa[c].x, qb[c].x, qa[c].y, qb[c].y};
            const uint32_t aa1[4] = {qa[c].z, qb[c].z, qa[c].w, qb[c].w};
#pragma unroll
            for (int nt = 0; nt < 8; nt++) {
                const int rB = nt * 8 + gID;
                const uint4 kv8 = *(const uint4*)(Ks + rB * 128 + ((c ^ (rB & 1)) << 6) + tIG * 16);
                const uint32_t bb0[2] = {kv8.x, kv8.y};
                const uint32_t bb1[2] = {kv8.z, kv8.w};
                mma_f16(sacc[nt], aa0, bb0);
                mma_f16(sacc[nt], aa1, bb1);
            }
        }

        // --- online softmax (rows qrow, qrow+8) ---
        float mx0 = -1e30f, mx1 = -1e30f;
#pragma unroll
        for (int nt = 0; nt < 8; nt++) {
            mx0 = fmaxf(mx0, fmaxf(sacc[nt][0], sacc[nt][1]));
            mx1 = fmaxf(mx1, fmaxf(sacc[nt][2], sacc[nt][3]));
        }
        mx0 = fmaxf(mx0, __shfl_xor_sync(0xffffffffu, mx0, 1));
        mx0 = fmaxf(mx0, __shfl_xor_sync(0xffffffffu, mx0, 2));
        mx1 = fmaxf(mx1, __shfl_xor_sync(0xffffffffu, mx1, 1));
        mx1 = fmaxf(mx1, __shfl_xor_sync(0xffffffffu, mx1, 2));

        const float mn0 = fmaxf(m0, mx0 * scale);
        const float mn1 = fmaxf(m1, mx1 * scale);
        const float corr0 = __expf(m0 - mn0);
        const float corr1 = __expf(m1 - mn1);

        float sum0 = 0.f, sum1 = 0.f;
#pragma unroll
        for (int nt = 0; nt < 8; nt++) {
            float p0 = h_round(__expf(sacc[nt][0] * scale - mn0));
            float p1 = h_round(__expf(sacc[nt][1] * scale - mn0));
            float p2 = h_round(__expf(sacc[nt][2] * scale - mn1));
            float p3 = h_round(__expf(sacc[nt][3] * scale - mn1));
            sum0 += p0 + p1; sum1 += p2 + p3;
            sacc[nt][0] = p0; sacc[nt][1] = p1; sacc[nt][2] = p2; sacc[nt][3] = p3;
        }
        sum0 += __shfl_xor_sync(0xffffffffu, sum0, 1);
        sum0 += __shfl_xor_sync(0xffffffffu, sum0, 2);
        sum1 += __shfl_xor_sync(0xffffffffu, sum1, 1);
        sum1 += __shfl_xor_sync(0xffffffffu, sum1, 2);

        l0 = l0 * corr0 + sum0; m0 = mn0;
        l1 = l1 * corr1 + sum1; m1 = mn1;
#pragma unroll
        for (int nt = 0; nt < 8; nt++) {
            oacc[nt][0] *= corr0; oacc[nt][1] *= corr0;
            oacc[nt][2] *= corr1; oacc[nt][3] *= corr1;
        }

        // --- write P (fp16, ph-perm kv, parity swizzle) ---
#pragma unroll
        for (int nt = 0; nt < 8; nt++) {
            const int c = nt * 8 + tIG * 2;
            const int cblk = c >> 5;
            const int phc = ph(c) & 31;    // ph(c+1) = ph(c)+1 (c even)
            *(__half2*)(Ps + qrow * 128 + ((cblk ^ (qrow & 1)) << 6) + phc * 2) =
                __floats2half2_rn(sacc[nt][0], sacc[nt][1]);
            *(__half2*)(Ps + (qrow + 8) * 128 + ((cblk ^ (qrow & 1)) << 6) + phc * 2) =
                __floats2half2_rn(sacc[nt][2], sacc[nt][3]);
        }
        __syncwarp();

        // --- O += P @ V ---
#pragma unroll
        for (int c = 0; c < 2; c++) {
            const uint4 pa = *(const uint4*)(Ps + qrow * 128       + ((c ^ (qrow & 1)) << 6) + tIG * 16);
            const uint4 pb = *(const uint4*)(Ps + (qrow + 8) * 128 + ((c ^ (qrow & 1)) << 6) + tIG * 16);
            const uint32_t aa0[4] = {pa.x, pb.x, pa.y, pb.y};
            const uint32_t aa1[4] = {pa.z, pb.z, pa.w, pb.w};
#pragma unroll
            for (int nt = 0; nt < 8; nt++) {
                const int rV = nt * 8 + gID;
                const uint4 vv = *(const uint4*)(VT + rV * 128 + ((c ^ (rV & 1)) << 6) + tIG * 16);
                const uint32_t bb0[2] = {vv.x, vv.y};
                const uint32_t bb1[2] = {vv.z, vv.w};
                mma_f16(oacc[nt], aa0, bb0);
                mma_f16(oacc[nt], aa1, bb1);
            }
        }
    }

    // --- write O as fp16 ph-permuted (feeds Wo GEMM) ---
    const float il0 = 1.f / l0, il1 = 1.f / l1;
    __half* orow0 = O + (row_base + qt * 64 + qrow) * H_;
    __half* orow1 = O + (row_base + qt * 64 + qrow + 8) * H_;
#pragma unroll
    for (int nt = 0; nt < 8; nt++) {
        const int c = h * HD_ + nt * 8 + tIG * 2;
        const int pc = ph(c);
        *(__half2*)(orow0 + pc) = __floats2half2_rn(oacc[nt][0] * il0, oacc[nt][1] * il0);
        *(__half2*)(orow1 + pc) = __floats2half2_rn(oacc[nt][2] * il1, oacc[nt][3] * il1);
    }
}

// ---------------------------------------------------------------------------
// Launch
// ---------------------------------------------------------------------------
extern "C" void kernel_launch(void* const* d_in, const int* in_sizes, int n_in,
                              void* d_out, int out_size)
{
    const float* x     = (const float*)d_in[0];
    const float* ln1_w = (const float*)d_in[1];
    const float* ln1_b = (const float*)d_in[2];
    const float* Wqkv  = (const float*)d_in[3];
    const float* bqkv  = (const float*)d_in[4];
    const float* Wo    = (const float*)d_in[5];
    const float* bo    = (const float*)d_in[6];
    const float* ln2_w = (const float*)d_in[7];
    const float* ln2_b = (const float*)d_in[8];
    const float* fc1_w = (const float*)d_in[9];
    const float* fc1_b = (const float*)d_in[10];
    const float* fc2_w = (const float*)d_in[11];
    const float* fc2_b = (const float*)d_in[12];
    float* out = (float*)d_out;

    __half *h, *qkv, *o, *h2, *a, *wqkvT, *woT, *w1T, *w2T;
    float *x2;
    cudaGetSymbolAddress((void**)&h,   g_h);
    cudaGetSymbolAddress((void**)&qkv, g_qkv);
    cudaGetSymbolAddress((void**)&o,   g_o);
    cudaGetSymbolAddress((void**)&x2,  g_x2);
    cudaGetSymbolAddress((void**)&h2,  g_h2);
    cudaGetSymbolAddress((void**)&a,   g_a);
    cudaGetSymbolAddress((void**)&wqkvT, g_wqkvT);
    cudaGetSymbolAddress((void**)&woT,   g_woT);
    cudaGetSymbolAddress((void**)&w1T,   g_w1T);
    cudaGetSymbolAddress((void**)&w2T,   g_w2T);

    cudaFuncSetAttribute(gemm_mma,
                         cudaFuncAttributeMaxDynamicSharedMemorySize, GEMM_SMEM);

    // 0) weight prepass: transpose + fp16 + ph-permute
    wtrans<<<dim3(QKV_N / 32, H_ / 32), 256>>>(Wqkv, wqkvT, H_, QKV_N);
    wtrans<<<dim3(H_ / 32,    H_ / 32), 256>>>(Wo,   woT,   H_, H_);
    wtrans<<<dim3(E_ / 32,    H_ / 32), 256>>>(fc1_w, w1T,  H_, E_);
    wtrans<<<dim3(H_ / 32,    E_ / 32), 256>>>(fc2_w, w2T,  E_, H_);

    // 1) LN1 (fp16 ph out)
    ln_kernel<<<M_, 256>>>(x, ln1_w, ln1_b, h);
    // 2) QKV projection (mode 3: Q,K fp16 ph; V plain fp16)
    gemm_mma<<<dim3(QKV_N / 128, M_ / 128), 256, GEMM_SMEM>>>(
        h, wqkvT, bqkv, nullptr, nullptr, qkv, M_, QKV_N, H_, 3);
    // 3) attention (fp16 tensor cores; fp16 ph out)
    attn_mma<<<dim3(S_ / 64, B_ * NH_), 128, ATTN_SMEM>>>(qkv, o);
    // 4) Wo + residual (fp32 out)
    gemm_mma<<<dim3(H_ / 128, M_ / 128), 256, GEMM_SMEM>>>(
        o, woT, bo, x, x2, nullptr, M_, H_, H_, 1);
    // 5) LN2 (fp16 ph out)
    ln_kernel<<<M_, 256>>>(x2, ln2_w, ln2_b, h2);
    // 6) FC1 + GELU (fp16 ph out)
    gemm_mma<<<dim3(E_ / 128, M_ / 128), 256, GEMM_SMEM>>>(
        h2, w1T, fc1_b, nullptr, nullptr, a, M_, E_, H_, 2);
    // 7) FC2 + residual -> out (fp32)
    gemm_mma<<<dim3(H_ / 128, M_ / 128), 256, GEMM_SMEM>>>(
        a, w2T, fc2_b, x2, out, nullptr, M_, H_, E_, 1);
}

// round 13
// speedup vs baseline: 1.8289x; 1.0148x over previous
#include <cuda_runtime.h>
#include <cuda_fp16.h>
#include <cstdint>
#include <math.h>

// ---------------------------------------------------------------------------
// Problem constants
// ---------------------------------------------------------------------------
#define B_   4
#define S_   2048
#define H_   1024
#define NH_  16
#define HD_  64
#define E_   4096
#define M_   (B_ * S_)          // 8192 tokens
#define QKV_N (3 * H_)          // 3072

// ---------------------------------------------------------------------------
// Scratch (device globals — no allocation allowed)
// ---------------------------------------------------------------------------
__device__ __half g_h  [M_ * H_];       // ln1 output (fp16, ph-perm)
__device__ __half g_qk [M_ * 2 * H_];   // Q,K fp16 ph-perm  [M][2048]
__device__ __half g_vt [64 * 64 * S_];  // V^T fp16: [bh][d][s], s ph-perm
__device__ __half g_o  [M_ * H_];       // attention output (fp16, ph-perm)
__device__ float  g_x2 [M_ * H_];       // x + attn@Wo + bo (plain fp32)
__device__ __half g_h2 [M_ * H_];       // ln2 output (fp16, ph-perm)
__device__ __half g_a  [M_ * E_];       // gelu(fc1) (fp16, ph-perm)
// transposed fp16 weights: [N][K], ph-permuted
__device__ __half g_wqkvT[QKV_N * H_];
__device__ __half g_woT  [H_ * H_];
__device__ __half g_w1T  [E_ * H_];
__device__ __half g_w2T  [H_ * E_];

// ---------------------------------------------------------------------------
// Helpers
// ---------------------------------------------------------------------------
__device__ __forceinline__ uint32_t smem_u32(const void* p) {
    uint32_t a;
    asm("{ .reg .u64 t; cvta.to.shared.u64 t, %1; cvt.u32.u64 %0, t; }"
        : "=r"(a) : "l"(p));
    return a;
}
// fp16 permutation within 32-blocks: thread tIG's halves {2t,2t+1,2t+8,2t+9}
// of both k16 sub-blocks land contiguously in its 16B LDS.128 slice.
__device__ __forceinline__ int ph(int k) {
    const int kk  = k & 15;
    const int blk = (k >> 4) & 1;
    const int o   = kk & 1;
    const int g   = (kk >> 1) & 3;
    const int w   = ((kk >> 3) << 1) | o;
    return (k & ~31) | (g * 8 + blk * 4 + w);
}
__device__ __forceinline__ float h_round(float x) {
    return __half2float(__float2half_rn(x));
}

__device__ __forceinline__ void mma_f16(float* c, const uint32_t* a, const uint32_t* b) {
    asm volatile(
        "mma.sync.aligned.m16n8k16.row.col.f32.f16.f16.f32 "
        "{%0,%1,%2,%3}, {%4,%5,%6,%7}, {%8,%9}, {%0,%1,%2,%3};"
        : "+f"(c[0]), "+f"(c[1]), "+f"(c[2]), "+f"(c[3])
        : "r"(a[0]), "r"(a[1]), "r"(a[2]), "r"(a[3]), "r"(b[0]), "r"(b[1]));
}

#define CP_ASYNC16(saddr, gptr) \
    asm volatile("cp.async.cg.shared.global [%0], [%1], 16;" \
        :: "r"(saddr), "l"(gptr) : "memory")
#define CP_COMMIT() asm volatile("cp.async.commit_group;" ::: "memory")

// ---------------------------------------------------------------------------
// Weight transpose + fp16-round + ph-permute:  W[K][N] fp32 -> WT[N][K] fp16
// ---------------------------------------------------------------------------
__global__ __launch_bounds__(256) void wtrans(
    const float* __restrict__ W, __half* __restrict__ WT, int K, int N)
{
    __shared__ float t[32][33];
    const int n0 = blockIdx.x * 32, k0 = blockIdx.y * 32;
    const int tx = threadIdx.x & 31, ty = threadIdx.x >> 5;
#pragma unroll
    for (int r = 0; r < 4; r++)
        t[ty + 8 * r][tx] = W[(size_t)(k0 + ty + 8 * r) * N + n0 + tx];
    __syncthreads();
#pragma unroll
    for (int r = 0; r < 4; r++) {
        const int n = n0 + ty + 8 * r;
        const int k = k0 + tx;
        WT[(size_t)n * K + ph(k)] = __float2half_rn(t[tx][ty + 8 * r]);
    }
}

// ---------------------------------------------------------------------------
// FP16 tensor-core GEMM (round-12 structure).
// mode 1: bias+residual -> C fp32; mode 2: bias+GELU -> Ch fp16 ph-perm;
// mode 3: bias -> QKV split: cols<2048 -> Ch (stride 2048, ph-perm);
//         cols>=2048 -> Vt transposed [bh][d][s] (s ph-perm)
// ---------------------------------------------------------------------------
#define STAGE_BYTES 32768                // A 16KB + B 16KB
#define GEMM_SMEM   (3 * STAGE_BYTES)    // 98304 per CTA

__global__ __launch_bounds__(256, 2) void gemm_mma(
    const __half* __restrict__ A, const __half* __restrict__ BT,
    const float* __restrict__ bias, const float* __restrict__ R,
    float* __restrict__ C, __half* __restrict__ Ch, __half* __restrict__ Vt,
    int M, int N, int K, int mode)
{
    extern __shared__ char smem[];
    const int tid = threadIdx.x;
    const int wid = tid >> 5, lane = tid & 31;
    const int gID = lane >> 2, tIG = lane & 3;
    const int warp_m = wid & 1, warp_n = wid >> 1;   // 2 x 4
    const int brow = blockIdx.y * 128, bcol = blockIdx.x * 128;
    const uint32_t sb = smem_u32(smem);

    const int lrow = tid >> 1;
    const int lseg = tid & 1;
    const __half* Ag = A  + (size_t)(brow + lrow) * K + lseg * 32;
    const __half* Bg = BT + (size_t)(bcol + lrow) * K + lseg * 32;
    const uint32_t aoff = (uint32_t)(lrow * 128 + ((lseg ^ (lrow & 1)) << 6));
    const uint32_t boff = aoff + 16384;

    float acc[4][4][4];
#pragma unroll
    for (int i = 0; i < 4; i++)
#pragma unroll
        for (int j = 0; j < 4; j++)
#pragma unroll
            for (int t = 0; t < 4; t++) acc[i][j][t] = 0.f;

    const int nt_tiles = K >> 6;

    auto issue = [&](int kt) {
        const uint32_t st = sb + (uint32_t)(kt % 3) * STAGE_BYTES;
        const __half* ga = Ag + kt * 64;
        const __half* gb = Bg + kt * 64;
#pragma unroll
        for (int i = 0; i < 4; i++) {
            CP_ASYNC16(st + aoff + i * 16, ga + i * 8);
            CP_ASYNC16(st + boff + i * 16, gb + i * 8);
        }
        CP_COMMIT();
    };

    issue(0); issue(1);

    const int m_base = warp_m * 64;
    const int n_base = warp_n * 32;

    for (int kt = 0; kt < nt_tiles; kt++) {
        if (kt + 1 < nt_tiles) asm volatile("cp.async.wait_group 1;" ::: "memory");
        else                   asm volatile("cp.async.wait_group 0;" ::: "memory");
        __syncthreads();
        if (kt + 2 < nt_tiles) issue(kt + 2);

        const char* stage = smem + (size_t)(kt % 3) * STAGE_BYTES;
        const uint32_t* as = (const uint32_t*)stage;
        const uint32_t* bs = as + 4096;

#pragma unroll
        for (int c = 0; c < 2; c++) {
            uint4 alow[4], ahigh[4], bv[4];
#pragma unroll
            for (int mt = 0; mt < 4; mt++) {
                const int r0 = m_base + mt * 16 + gID;
                const uint32_t* p = as + r0 * 32 + ((c ^ (r0 & 1)) << 4) + tIG * 4;
                alow[mt]  = *(const uint4*)p;
                ahigh[mt] = *(const uint4*)(p + 256);
            }
#pragma unroll
            for (int nt = 0; nt < 4; nt++) {
                const int rB = n_base + nt * 8 + gID;
                bv[nt] = *(const uint4*)(bs + rB * 32 + ((c ^ (rB & 1)) << 4) + tIG * 4);
            }
#pragma unroll
            for (int mt = 0; mt < 4; mt++) {
                const uint32_t aa0[4] = {alow[mt].x, ahigh[mt].x, alow[mt].y, ahigh[mt].y};
                const uint32_t aa1[4] = {alow[mt].z, ahigh[mt].z, alow[mt].w, ahigh[mt].w};
#pragma unroll
                for (int nt = 0; nt < 4; nt++) {
                    const uint32_t bb0[2] = {bv[nt].x, bv[nt].y};
                    const uint32_t bb1[2] = {bv[nt].z, bv[nt].w};
                    mma_f16(acc[mt][nt], aa0, bb0);
                    mma_f16(acc[mt][nt], aa1, bb1);
                }
            }
        }
    }

    // --- epilogue ---
#pragma unroll
    for (int mt = 0; mt < 4; mt++) {
#pragma unroll
        for (int half_ = 0; half_ < 2; half_++) {
            const int row = brow + m_base + mt * 16 + gID + half_ * 8;
            float* crow = C + (size_t)row * N;
            const float* rrow = (mode == 1) ? (R + (size_t)row * N) : nullptr;
#pragma unroll
            for (int nt = 0; nt < 4; nt++) {
                const int col = bcol + n_base + nt * 8 + tIG * 2;
                float v0 = acc[mt][nt][half_ * 2 + 0];
                float v1 = acc[mt][nt][half_ * 2 + 1];
                const float2 bb = *(const float2*)(bias + col);
                v0 += bb.x; v1 += bb.y;
                if (mode == 1) {
                    const float2 rr = *(const float2*)(rrow + col);
                    v0 += rr.x; v1 += rr.y;
                    *(float2*)(crow + col) = make_float2(v0, v1);
                } else if (mode == 2) {
                    v0 = 0.5f * v0 * (1.f + erff(v0 * 0.70710678118654752f));
                    v1 = 0.5f * v1 * (1.f + erff(v1 * 0.70710678118654752f));
                    *(__half2*)(Ch + (size_t)row * N + ph(col)) =
                        __floats2half2_rn(v0, v1);
                } else { // mode 3: Q,K -> Ch [M][2048]; V -> Vt [bh][d][s]
                    if (col < 2 * H_) {
                        __half* chrow = Ch + (size_t)row * (2 * H_);
                        *(__half2*)(chrow + ph(col)) = __floats2half2_rn(v0, v1);
                    } else {
                        const int bq = row >> 11, s = row & 2047;
                        const int dg = col - 2 * H_;
                        const int hh = dg >> 6, d0 = dg & 63;
                        __half* vrow = Vt + (((size_t)(bq * 16 + hh) * 64 + d0) * S_) + ph(s);
                        vrow[0]  = __float2half_rn(v0);
                        vrow[S_] = __float2half_rn(v1);
                    }
                }
            }
        }
    }
}

// ---------------------------------------------------------------------------
// LayerNorm: one block per row of 1024; output fp16, ph-permuted
// ---------------------------------------------------------------------------
__global__ __launch_bounds__(256) void ln_kernel(
    const float* __restrict__ x, const float* __restrict__ w,
    const float* __restrict__ b, __half* __restrict__ out)
{
    const int row = blockIdx.x;
    const int tid = threadIdx.x;
    const float* xr = x + (size_t)row * H_;

    float v[4];
    float s = 0.f, s2 = 0.f;
#pragma unroll
    for (int i = 0; i < 4; i++) {
        v[i] = xr[tid + 256 * i];
        s += v[i];
        s2 += v[i] * v[i];
    }
#pragma unroll
    for (int off = 16; off > 0; off >>= 1) {
        s  += __shfl_xor_sync(0xffffffffu, s,  off);
        s2 += __shfl_xor_sync(0xffffffffu, s2, off);
    }
    __shared__ float red[8], red2[8];
    const int wid = tid >> 5, lane = tid & 31;
    if (lane == 0) { red[wid] = s; red2[wid] = s2; }
    __syncthreads();
    if (tid < 32) {
        float a = (tid < 8) ? red[tid]  : 0.f;
        float c = (tid < 8) ? red2[tid] : 0.f;
#pragma unroll
        for (int off = 4; off > 0; off >>= 1) {
            a += __shfl_xor_sync(0xffffffffu, a, off);
            c += __shfl_xor_sync(0xffffffffu, c, off);
        }
        if (tid == 0) { red[0] = a; red2[0] = c; }
    }
    __syncthreads();
    const float mu  = red[0] * (1.f / H_);
    const float var = red2[0] * (1.f / H_) - mu * mu;
    const float rstd = rsqrtf(var + 1e-5f);

    __half* orow = out + (size_t)row * H_;
#pragma unroll
    for (int i = 0; i < 4; i++) {
        const int c = tid + 256 * i;
        orow[ph(c)] = __float2half_rn((v[i] - mu) * rstd * w[c] + b[c]);
    }
}

// ---------------------------------------------------------------------------
// FP16 flash attention, Q-tile 128. Grid (16, 64), 256 threads = 8 warps.
// Q/K from g_qk [M][2048] ph-perm; V from g_vt [bh][d][s] (s ph-perm).
// All tiles via cp.async; 128B rows with 64B parity XOR swizzle.
// ---------------------------------------------------------------------------
#define ATTN_SMEM (16384 + 8192 + 8192 + 16384)   // Qs, Ks, VT, Ps = 48KB

__global__ __launch_bounds__(256) void attn_mma(
    const __half* __restrict__ qk, const __half* __restrict__ vt,
    __half* __restrict__ O)
{
    extern __shared__ char asmem[];
    char* Qs = asmem;             // [128 q rows][128B]
    char* Ks = Qs + 16384;        // [64 kv rows][128B]
    char* VT = Ks + 8192;         // [64 d rows][128B kv]
    char* Ps = VT + 8192;         // [128 q rows][128B kv]

    const int qt = blockIdx.x, bh = blockIdx.y;
    const int b = bh >> 4, h = bh & 15;
    const int tid = threadIdx.x, wid = tid >> 5, lane = tid & 31;
    const int gID = lane >> 2, tIG = lane & 3;
    const size_t row_base = (size_t)b * S_;
    const int qoff = h * HD_, koff = H_ + h * HD_;
    const __half* vt_bh = vt + (size_t)bh * 64 * S_;

    // --- Q tile (128 rows) ---
    {
        const int r = tid >> 1, seg = tid & 1;
        const __half* gq = qk + (row_base + qt * 128 + r) * (2 * H_) + qoff + seg * 32;
        const uint32_t sq = smem_u32(Qs) + r * 128 + ((seg ^ (r & 1)) << 6);
#pragma unroll
        for (int j = 0; j < 4; j++) CP_ASYNC16(sq + j * 16, gq + j * 8);
        CP_COMMIT();
    }
    asm volatile("cp.async.wait_group 0;" ::: "memory");
    __syncthreads();

    const int qrow = wid * 16 + gID;
    uint4 qa[2], qb[2];
#pragma unroll
    for (int c = 0; c < 2; c++) {
        qa[c] = *(const uint4*)(Qs + qrow * 128       + ((c ^ (qrow & 1)) << 6) + tIG * 16);
        qb[c] = *(const uint4*)(Qs + (qrow + 8) * 128 + ((c ^ (qrow & 1)) << 6) + tIG * 16);
    }

    float m0 = -1e30f, m1 = -1e30f, l0 = 0.f, l1 = 0.f;
    float oacc[8][4];
#pragma unroll
    for (int i = 0; i < 8; i++)
#pragma unroll
        for (int j = 0; j < 4; j++) oacc[i][j] = 0.f;

    const float scale = 0.125f;

    for (int kt = 0; kt < S_ / 64; kt++) {
        __syncthreads();

        // K tile: 64 rows x 128B; V tile: 64 d-rows x 128B — both cp.async
        {
            const int r = tid >> 2, q = tid & 3;
            const uint32_t dsto = (uint32_t)(r * 128 + (((q >> 1) ^ (r & 1)) << 6) + (q & 1) * 32);
            const __half* gk = qk + (row_base + kt * 64 + r) * (2 * H_) + koff + q * 16;
            const uint32_t sk = smem_u32(Ks) + dsto;
            CP_ASYNC16(sk,      gk);
            CP_ASYNC16(sk + 16, gk + 8);
            const __half* gv = vt_bh + (size_t)r * S_ + kt * 64 + q * 16;
            const uint32_t sv = smem_u32(VT) + dsto;
            CP_ASYNC16(sv,      gv);
            CP_ASYNC16(sv + 16, gv + 8);
            CP_COMMIT();
        }
        asm volatile("cp.async.wait_group 0;" ::: "memory");
        __syncthreads();

        // --- S = Q @ K^T ---
        float sacc[8][4];
#pragma unroll
        for (int i = 0; i < 8; i++)
#pragma unroll
            for (int j = 0; j < 4; j++) sacc[i][j] = 0.f;

#pragma unroll
        for (int c = 0; c < 2; c++) {
            const uint32_t aa0[4] = {qa[c].x, qb[c].x, qa[c].y, qb[c].y};
            const uint32_t aa1[4] = {qa[c].z, qb[c].z, qa[c].w, qb[c].w};
#pragma unroll
            for (int nt = 0; nt < 8; nt++) {
                const int rB = nt * 8 + gID;
                const uint4 kv8 = *(const uint4*)(Ks + rB * 128 + ((c ^ (rB & 1)) << 6) + tIG * 16);
                const uint32_t bb0[2] = {kv8.x, kv8.y};
                const uint32_t bb1[2] = {kv8.z, kv8.w};
                mma_f16(sacc[nt], aa0, bb0);
                mma_f16(sacc[nt], aa1, bb1);
            }
        }

        // --- online softmax ---
        float mx0 = -1e30f, mx1 = -1e30f;
#pragma unroll
        for (int nt = 0; nt < 8; nt++) {
            mx0 = fmaxf(mx0, fmaxf(sacc[nt][0], sacc[nt][1]));
            mx1 = fmaxf(mx1, fmaxf(sacc[nt][2], sacc[nt][3]));
        }
        mx0 = fmaxf(mx0, __shfl_xor_sync(0xffffffffu, mx0, 1));
        mx0 = fmaxf(mx0, __shfl_xor_sync(0xffffffffu, mx0, 2));
        mx1 = fmaxf(mx1, __shfl_xor_sync(0xffffffffu, mx1, 1));
        mx1 = fmaxf(mx1, __shfl_xor_sync(0xffffffffu, mx1, 2));

        const float mn0 = fmaxf(m0, mx0 * scale);
        const float mn1 = fmaxf(m1, mx1 * scale);
        const float corr0 = __expf(m0 - mn0);
        const float corr1 = __expf(m1 - mn1);

        float sum0 = 0.f, sum1 = 0.f;
#pragma unroll
        for (int nt = 0; nt < 8; nt++) {
            float p0 = h_round(__expf(sacc[nt][0] * scale - mn0));
            float p1 = h_round(__expf(sacc[nt][1] * scale - mn0));
            float p2 = h_round(__expf(sacc[nt][2] * scale - mn1));
            float p3 = h_round(__expf(sacc[nt][3] * scale - mn1));
            sum0 += p0 + p1; sum1 += p2 + p3;
            sacc[nt][0] = p0; sacc[nt][1] = p1; sacc[nt][2] = p2; sacc[nt][3] = p3;
        }
        sum0 += __shfl_xor_sync(0xffffffffu, sum0, 1);
        sum0 += __shfl_xor_sync(0xffffffffu, sum0, 2);
        sum1 += __shfl_xor_sync(0xffffffffu, sum1, 1);
        sum1 += __shfl_xor_sync(0xffffffffu, sum1, 2);

        l0 = l0 * corr0 + sum0; m0 = mn0;
        l1 = l1 * corr1 + sum1; m1 = mn1;
#pragma unroll
        for (int nt = 0; nt < 8; nt++) {
            oacc[nt][0] *= corr0; oacc[nt][1] *= corr0;
            oacc[nt][2] *= corr1; oacc[nt][3] *= corr1;
        }

        // --- write P (fp16, ph-perm kv, parity swizzle) ---
#pragma unroll
        for (int nt = 0; nt < 8; nt++) {
            const int c = nt * 8 + tIG * 2;
            const int cblk = c >> 5;
            const int phc = ph(c) & 31;
            *(__half2*)(Ps + qrow * 128 + ((cblk ^ (qrow & 1)) << 6) + phc * 2) =
                __floats2half2_rn(sacc[nt][0], sacc[nt][1]);
            *(__half2*)(Ps + (qrow + 8) * 128 + ((cblk ^ (qrow & 1)) << 6) + phc * 2) =
                __floats2half2_rn(sacc[nt][2], sacc[nt][3]);
        }
        __syncwarp();

        // --- O += P @ V ---
#pragma unroll
        for (int c = 0; c < 2; c++) {
            const uint4 pa = *(const uint4*)(Ps + qrow * 128       + ((c ^ (qrow & 1)) << 6) + tIG * 16);
            const uint4 pb = *(const uint4*)(Ps + (qrow + 8) * 128 + ((c ^ (qrow & 1)) << 6) + tIG * 16);
            const uint32_t aa0[4] = {pa.x, pb.x, pa.y, pb.y};
            const uint32_t aa1[4] = {pa.z, pb.z, pa.w, pb.w};
#pragma unroll
            for (int nt = 0; nt < 8; nt++) {
                const int rV = nt * 8 + gID;
                const uint4 vv = *(const uint4*)(VT + rV * 128 + ((c ^ (rV & 1)) << 6) + tIG * 16);
                const uint32_t bb0[2] = {vv.x, vv.y};
                const uint32_t bb1[2] = {vv.z, vv.w};
                mma_f16(oacc[nt], aa0, bb0);
                mma_f16(oacc[nt], aa1, bb1);
            }
        }
    }

    // --- write O as fp16 ph-permuted (feeds Wo GEMM) ---
    const float il0 = 1.f / l0, il1 = 1.f / l1;
    __half* orow0 = O + (row_base + qt * 128 + qrow) * H_;
    __half* orow1 = O + (row_base + qt * 128 + qrow + 8) * H_;
#pragma unroll
    for (int nt = 0; nt < 8; nt++) {
        const int c = h * HD_ + nt * 8 + tIG * 2;
        const int pc = ph(c);
        *(__half2*)(orow0 + pc) = __floats2half2_rn(oacc[nt][0] * il0, oacc[nt][1] * il0);
        *(__half2*)(orow1 + pc) = __floats2half2_rn(oacc[nt][2] * il1, oacc[nt][3] * il1);
    }
}

// ---------------------------------------------------------------------------
// Launch
// ---------------------------------------------------------------------------
extern "C" void kernel_launch(void* const* d_in, const int* in_sizes, int n_in,
                              void* d_out, int out_size)
{
    const float* x     = (const float*)d_in[0];
    const float* ln1_w = (const float*)d_in[1];
    const float* ln1_b = (const float*)d_in[2];
    const float* Wqkv  = (const float*)d_in[3];
    const float* bqkv  = (const float*)d_in[4];
    const float* Wo    = (const float*)d_in[5];
    const float* bo    = (const float*)d_in[6];
    const float* ln2_w = (const float*)d_in[7];
    const float* ln2_b = (const float*)d_in[8];
    const float* fc1_w = (const float*)d_in[9];
    const float* fc1_b = (const float*)d_in[10];
    const float* fc2_w = (const float*)d_in[11];
    const float* fc2_b = (const float*)d_in[12];
    float* out = (float*)d_out;

    __half *h, *qk, *vt, *o, *h2, *a, *wqkvT, *woT, *w1T, *w2T;
    float *x2;
    cudaGetSymbolAddress((void**)&h,   g_h);
    cudaGetSymbolAddress((void**)&qk,  g_qk);
    cudaGetSymbolAddress((void**)&vt,  g_vt);
    cudaGetSymbolAddress((void**)&o,   g_o);
    cudaGetSymbolAddress((void**)&x2,  g_x2);
    cudaGetSymbolAddress((void**)&h2,  g_h2);
    cudaGetSymbolAddress((void**)&a,   g_a);
    cudaGetSymbolAddress((void**)&wqkvT, g_wqkvT);
    cudaGetSymbolAddress((void**)&woT,   g_woT);
    cudaGetSymbolAddress((void**)&w1T,   g_w1T);
    cudaGetSymbolAddress((void**)&w2T,   g_w2T);

    cudaFuncSetAttribute(gemm_mma,
                         cudaFuncAttributeMaxDynamicSharedMemorySize, GEMM_SMEM);
    cudaFuncSetAttribute(attn_mma,
                         cudaFuncAttributeMaxDynamicSharedMemorySize, ATTN_SMEM);

    // 0) weight prepass: transpose + fp16 + ph-permute
    wtrans<<<dim3(QKV_N / 32, H_ / 32), 256>>>(Wqkv, wqkvT, H_, QKV_N);
    wtrans<<<dim3(H_ / 32,    H_ / 32), 256>>>(Wo,   woT,   H_, H_);
    wtrans<<<dim3(E_ / 32,    H_ / 32), 256>>>(fc1_w, w1T,  H_, E_);
    wtrans<<<dim3(H_ / 32,    E_ / 32), 256>>>(fc2_w, w2T,  E_, H_);

    // 1) LN1 (fp16 ph out)
    ln_kernel<<<M_, 256>>>(x, ln1_w, ln1_b, h);
    // 2) QKV projection (mode 3: Q,K -> qk; V -> vt transposed)
    gemm_mma<<<dim3(QKV_N / 128, M_ / 128), 256, GEMM_SMEM>>>(
        h, wqkvT, bqkv, nullptr, nullptr, qk, vt, M_, QKV_N, H_, 3);
    // 3) attention (fp16 tensor cores, Q-tile 128; fp16 ph out)
    attn_mma<<<dim3(S_ / 128, B_ * NH_), 256, ATTN_SMEM>>>(qk, vt, o);
    // 4) Wo + residual (fp32 out)
    gemm_mma<<<dim3(H_ / 128, M_ / 128), 256, GEMM_SMEM>>>(
        o, woT, bo, x, x2, nullptr, nullptr, M_, H_, H_, 1);
    // 5) LN2 (fp16 ph out)
    ln_kernel<<<M_, 256>>>(x2, ln2_w, ln2_b, h2);
    // 6) FC1 + GELU (fp16 ph out)
    gemm_mma<<<dim3(E_ / 128, M_ / 128), 256, GEMM_SMEM>>>(
        h2, w1T, fc1_b, nullptr, nullptr, a, nullptr, M_, E_, H_, 2);
    // 7) FC2 + residual -> out (fp32)
    gemm_mma<<<dim3(H_ / 128, M_ / 128), 256, GEMM_SMEM>>>(
        a, w2T, fc2_b, x2, out, nullptr, nullptr, M_, H_, E_, 1);
}

// round 14
// speedup vs baseline: 2.0177x; 1.1033x over previous
#include <cuda_runtime.h>
#include <cuda_fp16.h>
#include <cstdint>
#include <math.h>

// ---------------------------------------------------------------------------
// Problem constants
// ---------------------------------------------------------------------------
#define B_   4
#define S_   2048
#define H_   1024
#define NH_  16
#define HD_  64
#define E_   4096
#define M_   (B_ * S_)          // 8192 tokens
#define QKV_N (3 * H_)          // 3072

// ---------------------------------------------------------------------------
// Scratch (device globals — no allocation allowed)
// ---------------------------------------------------------------------------
__device__ __half g_h  [M_ * H_];       // ln1 output (fp16, ph-perm)
__device__ __half g_qk [M_ * 2 * H_];   // Q,K fp16 ph-perm  [M][2048]
__device__ __half g_v  [M_ * H_];       // V fp16 plain rows [M][1024]
__device__ __half g_vt [64 * 64 * S_];  // V^T fp16: [bh][d][s], s ph-perm
__device__ __half g_o  [M_ * H_];       // attention output (fp16, ph-perm)
__device__ float  g_x2 [M_ * H_];       // x + attn@Wo + bo (plain fp32)
__device__ __half g_h2 [M_ * H_];       // ln2 output (fp16, ph-perm)
__device__ __half g_a  [M_ * E_];       // gelu(fc1) (fp16, ph-perm)
// transposed fp16 weights: [N][K], ph-permuted
__device__ __half g_wqkvT[QKV_N * H_];
__device__ __half g_woT  [H_ * H_];
__device__ __half g_w1T  [E_ * H_];
__device__ __half g_w2T  [H_ * E_];

// ---------------------------------------------------------------------------
// Helpers
// ---------------------------------------------------------------------------
__device__ __forceinline__ uint32_t smem_u32(const void* p) {
    uint32_t a;
    asm("{ .reg .u64 t; cvta.to.shared.u64 t, %1; cvt.u32.u64 %0, t; }"
        : "=r"(a) : "l"(p));
    return a;
}
// fp16 permutation within 32-blocks: thread tIG's halves {2t,2t+1,2t+8,2t+9}
// of both k16 sub-blocks land contiguously in its 16B LDS.128 slice.
__device__ __forceinline__ int ph(int k) {
    const int kk  = k & 15;
    const int blk = (k >> 4) & 1;
    const int o   = kk & 1;
    const int g   = (kk >> 1) & 3;
    const int w   = ((kk >> 3) << 1) | o;
    return (k & ~31) | (g * 8 + blk * 4 + w);
}
__device__ __forceinline__ float h_round(float x) {
    return __half2float(__float2half_rn(x));
}

__device__ __forceinline__ void mma_f16(float* c, const uint32_t* a, const uint32_t* b) {
    asm volatile(
        "mma.sync.aligned.m16n8k16.row.col.f32.f16.f16.f32 "
        "{%0,%1,%2,%3}, {%4,%5,%6,%7}, {%8,%9}, {%0,%1,%2,%3};"
        : "+f"(c[0]), "+f"(c[1]), "+f"(c[2]), "+f"(c[3])
        : "r"(a[0]), "r"(a[1]), "r"(a[2]), "r"(a[3]), "r"(b[0]), "r"(b[1]));
}

#define CP_ASYNC16(saddr, gptr) \
    asm volatile("cp.async.cg.shared.global [%0], [%1], 16;" \
        :: "r"(saddr), "l"(gptr) : "memory")
#define CP_COMMIT() asm volatile("cp.async.commit_group;" ::: "memory")

// ---------------------------------------------------------------------------
// Weight transpose + fp16-round + ph-permute:  W[K][N] fp32 -> WT[N][K] fp16
// ---------------------------------------------------------------------------
__global__ __launch_bounds__(256) void wtrans(
    const float* __restrict__ W, __half* __restrict__ WT, int K, int N)
{
    __shared__ float t[32][33];
    const int n0 = blockIdx.x * 32, k0 = blockIdx.y * 32;
    const int tx = threadIdx.x & 31, ty = threadIdx.x >> 5;
#pragma unroll
    for (int r = 0; r < 4; r++)
        t[ty + 8 * r][tx] = W[(size_t)(k0 + ty + 8 * r) * N + n0 + tx];
    __syncthreads();
#pragma unroll
    for (int r = 0; r < 4; r++) {
        const int n = n0 + ty + 8 * r;
        const int k = k0 + tx;
        WT[(size_t)n * K + ph(k)] = __float2half_rn(t[tx][ty + 8 * r]);
    }
}

// ---------------------------------------------------------------------------
// V transpose: g_v [M][1024] plain -> g_vt [bh][d][s] (s ph-perm within 32)
// grid (S_/64, B_*NH_), 256 threads; coalesced loads, 64B-contig stores.
// ---------------------------------------------------------------------------
__global__ __launch_bounds__(256) void vtrans(
    const __half* __restrict__ V, __half* __restrict__ VT)
{
    __shared__ __half tile[64][72];
    const int kt = blockIdx.x, bh = blockIdx.y;
    const int b = bh >> 4, h = bh & 15;
    const size_t row_base = (size_t)b * S_;
    const int t = threadIdx.x;

    {
        const int srow = t >> 2, seg = t & 3;
        const uint4* src = (const uint4*)(V + (row_base + kt * 64 + srow) * H_ + h * 64 + seg * 16);
        *(uint4*)&tile[srow][seg * 16]     = src[0];
        *(uint4*)&tile[srow][seg * 16 + 8] = src[1];
    }
    __syncthreads();
    if (t < 128) {
        const int d = t >> 1, blk = t & 1;
        __half buf[32];
#pragma unroll
        for (int i = 0; i < 32; i++)
            buf[ph(i)] = tile[blk * 32 + i][d];
        uint4* dst = (uint4*)(VT + ((size_t)bh * 64 + d) * S_ + kt * 64 + blk * 32);
        const uint4* bsrc = (const uint4*)buf;
#pragma unroll
        for (int j = 0; j < 4; j++) dst[j] = bsrc[j];
    }
}

// ---------------------------------------------------------------------------
// FP16 tensor-core GEMM (round-12 structure).
// mode 1: bias+residual -> C fp32; mode 2: bias+GELU -> Ch fp16 ph-perm;
// mode 3: bias -> QKV split: cols<2048 -> Ch [M][2048] ph-perm;
//         cols>=2048 -> Vt (plain V buffer [M][1024], coalesced half2)
// ---------------------------------------------------------------------------
#define STAGE_BYTES 32768                // A 16KB + B 16KB
#define GEMM_SMEM   (3 * STAGE_BYTES)    // 98304 per CTA

__global__ __launch_bounds__(256, 2) void gemm_mma(
    const __half* __restrict__ A, const __half* __restrict__ BT,
    const float* __restrict__ bias, const float* __restrict__ R,
    float* __restrict__ C, __half* __restrict__ Ch, __half* __restrict__ Vt,
    int M, int N, int K, int mode)
{
    extern __shared__ char smem[];
    const int tid = threadIdx.x;
    const int wid = tid >> 5, lane = tid & 31;
    const int gID = lane >> 2, tIG = lane & 3;
    const int warp_m = wid & 1, warp_n = wid >> 1;   // 2 x 4
    const int brow = blockIdx.y * 128, bcol = blockIdx.x * 128;
    const uint32_t sb = smem_u32(smem);

    const int lrow = tid >> 1;
    const int lseg = tid & 1;
    const __half* Ag = A  + (size_t)(brow + lrow) * K + lseg * 32;
    const __half* Bg = BT + (size_t)(bcol + lrow) * K + lseg * 32;
    const uint32_t aoff = (uint32_t)(lrow * 128 + ((lseg ^ (lrow & 1)) << 6));
    const uint32_t boff = aoff + 16384;

    float acc[4][4][4];
#pragma unroll
    for (int i = 0; i < 4; i++)
#pragma unroll
        for (int j = 0; j < 4; j++)
#pragma unroll
            for (int t = 0; t < 4; t++) acc[i][j][t] = 0.f;

    const int nt_tiles = K >> 6;

    auto issue = [&](int kt) {
        const uint32_t st = sb + (uint32_t)(kt % 3) * STAGE_BYTES;
        const __half* ga = Ag + kt * 64;
        const __half* gb = Bg + kt * 64;
#pragma unroll
        for (int i = 0; i < 4; i++) {
            CP_ASYNC16(st + aoff + i * 16, ga + i * 8);
            CP_ASYNC16(st + boff + i * 16, gb + i * 8);
        }
        CP_COMMIT();
    };

    issue(0); issue(1);

    const int m_base = warp_m * 64;
    const int n_base = warp_n * 32;

    for (int kt = 0; kt < nt_tiles; kt++) {
        if (kt + 1 < nt_tiles) asm volatile("cp.async.wait_group 1;" ::: "memory");
        else                   asm volatile("cp.async.wait_group 0;" ::: "memory");
        __syncthreads();
        if (kt + 2 < nt_tiles) issue(kt + 2);

        const char* stage = smem + (size_t)(kt % 3) * STAGE_BYTES;
        const uint32_t* as = (const uint32_t*)stage;
        const uint32_t* bs = as + 4096;

#pragma unroll
        for (int c = 0; c < 2; c++) {
            uint4 alow[4], ahigh[4], bv[4];
#pragma unroll
            for (int mt = 0; mt < 4; mt++) {
                const int r0 = m_base + mt * 16 + gID;
                const uint32_t* p = as + r0 * 32 + ((c ^ (r0 & 1)) << 4) + tIG * 4;
                alow[mt]  = *(const uint4*)p;
                ahigh[mt] = *(const uint4*)(p + 256);
            }
#pragma unroll
            for (int nt = 0; nt < 4; nt++) {
                const int rB = n_base + nt * 8 + gID;
                bv[nt] = *(const uint4*)(bs + rB * 32 + ((c ^ (rB & 1)) << 4) + tIG * 4);
            }
#pragma unroll
            for (int mt = 0; mt < 4; mt++) {
                const uint32_t aa0[4] = {alow[mt].x, ahigh[mt].x, alow[mt].y, ahigh[mt].y};
                const uint32_t aa1[4] = {alow[mt].z, ahigh[mt].z, alow[mt].w, ahigh[mt].w};
#pragma unroll
                for (int nt = 0; nt < 4; nt++) {
                    const uint32_t bb0[2] = {bv[nt].x, bv[nt].y};
                    const uint32_t bb1[2] = {bv[nt].z, bv[nt].w};
                    mma_f16(acc[mt][nt], aa0, bb0);
                    mma_f16(acc[mt][nt], aa1, bb1);
                }
            }
        }
    }

    // --- epilogue ---
#pragma unroll
    for (int mt = 0; mt < 4; mt++) {
#pragma unroll
        for (int half_ = 0; half_ < 2; half_++) {
            const int row = brow + m_base + mt * 16 + gID + half_ * 8;
            float* crow = C + (size_t)row * N;
            const float* rrow = (mode == 1) ? (R + (size_t)row * N) : nullptr;
#pragma unroll
            for (int nt = 0; nt < 4; nt++) {
                const int col = bcol + n_base + nt * 8 + tIG * 2;
                float v0 = acc[mt][nt][half_ * 2 + 0];
                float v1 = acc[mt][nt][half_ * 2 + 1];
                const float2 bb = *(const float2*)(bias + col);
                v0 += bb.x; v1 += bb.y;
                if (mode == 1) {
                    const float2 rr = *(const float2*)(rrow + col);
                    v0 += rr.x; v1 += rr.y;
                    *(float2*)(crow + col) = make_float2(v0, v1);
                } else if (mode == 2) {
                    v0 = 0.5f * v0 * (1.f + erff(v0 * 0.70710678118654752f));
                    v1 = 0.5f * v1 * (1.f + erff(v1 * 0.70710678118654752f));
                    *(__half2*)(Ch + (size_t)row * N + ph(col)) =
                        __floats2half2_rn(v0, v1);
                } else { // mode 3: Q,K -> Ch [M][2048]; V plain -> Vt [M][1024]
                    if (col < 2 * H_) {
                        __half* chrow = Ch + (size_t)row * (2 * H_);
                        *(__half2*)(chrow + ph(col)) = __floats2half2_rn(v0, v1);
                    } else {
                        *(__half2*)(Vt + (size_t)row * H_ + (col - 2 * H_)) =
                            __floats2half2_rn(v0, v1);
                    }
                }
            }
        }
    }
}

// ---------------------------------------------------------------------------
// LayerNorm: one block per row of 1024; output fp16, ph-permuted
// ---------------------------------------------------------------------------
__global__ __launch_bounds__(256) void ln_kernel(
    const float* __restrict__ x, const float* __restrict__ w,
    const float* __restrict__ b, __half* __restrict__ out)
{
    const int row = blockIdx.x;
    const int tid = threadIdx.x;
    const float* xr = x + (size_t)row * H_;

    float v[4];
    float s = 0.f, s2 = 0.f;
#pragma unroll
    for (int i = 0; i < 4; i++) {
        v[i] = xr[tid + 256 * i];
        s += v[i];
        s2 += v[i] * v[i];
    }
#pragma unroll
    for (int off = 16; off > 0; off >>= 1) {
        s  += __shfl_xor_sync(0xffffffffu, s,  off);
        s2 += __shfl_xor_sync(0xffffffffu, s2, off);
    }
    __shared__ float red[8], red2[8];
    const int wid = tid >> 5, lane = tid & 31;
    if (lane == 0) { red[wid] = s; red2[wid] = s2; }
    __syncthreads();
    if (tid < 32) {
        float a = (tid < 8) ? red[tid]  : 0.f;
        float c = (tid < 8) ? red2[tid] : 0.f;
#pragma unroll
        for (int off = 4; off > 0; off >>= 1) {
            a += __shfl_xor_sync(0xffffffffu, a, off);
            c += __shfl_xor_sync(0xffffffffu, c, off);
        }
        if (tid == 0) { red[0] = a; red2[0] = c; }
    }
    __syncthreads();
    const float mu  = red[0] * (1.f / H_);
    const float var = red2[0] * (1.f / H_) - mu * mu;
    const float rstd = rsqrtf(var + 1e-5f);

    __half* orow = out + (size_t)row * H_;
#pragma unroll
    for (int i = 0; i < 4; i++) {
        const int c = tid + 256 * i;
        orow[ph(c)] = __float2half_rn((v[i] - mu) * rstd * w[c] + b[c]);
    }
}

// ---------------------------------------------------------------------------
// FP16 flash attention, Q-tile 128, 2-stage K/V cp.async pipeline.
// Grid (16, 64), 256 threads = 8 warps. Q/K from g_qk; V from g_vt.
// ---------------------------------------------------------------------------
#define ATTN_SMEM (16384 + 2 * 8192 + 2 * 8192 + 16384)   // 64KB

__global__ __launch_bounds__(256) void attn_mma(
    const __half* __restrict__ qk, const __half* __restrict__ vt,
    __half* __restrict__ O)
{
    extern __shared__ char asmem[];
    char* Qs  = asmem;             // [128 q rows][128B]
    char* KsB = Qs + 16384;        // 2 x [64 kv rows][128B]
    char* VTB = KsB + 16384;       // 2 x [64 d rows][128B kv]
    char* Ps  = VTB + 16384;       // [128 q rows][128B kv]

    const int qt = blockIdx.x, bh = blockIdx.y;
    const int b = bh >> 4, h = bh & 15;
    const int tid = threadIdx.x, wid = tid >> 5, lane = tid & 31;
    const int gID = lane >> 2, tIG = lane & 3;
    const size_t row_base = (size_t)b * S_;
    const int qoff = h * HD_, koff = H_ + h * HD_;
    const __half* vt_bh = vt + (size_t)bh * 64 * S_;

    auto issueKV = [&](int kt) {
        char* Ks = KsB + (kt & 1) * 8192;
        char* VT = VTB + (kt & 1) * 8192;
        const int r = tid >> 2, q = tid & 3;
        const uint32_t dsto = (uint32_t)(r * 128 + (((q >> 1) ^ (r & 1)) << 6) + (q & 1) * 32);
        const __half* gk = qk + (row_base + kt * 64 + r) * (2 * H_) + koff + q * 16;
        const uint32_t sk = smem_u32(Ks) + dsto;
        CP_ASYNC16(sk,      gk);
        CP_ASYNC16(sk + 16, gk + 8);
        const __half* gv = vt_bh + (size_t)r * S_ + kt * 64 + q * 16;
        const uint32_t sv = smem_u32(VT) + dsto;
        CP_ASYNC16(sv,      gv);
        CP_ASYNC16(sv + 16, gv + 8);
        CP_COMMIT();
    };

    // --- Q tile (own commit group) ---
    {
        const int r = tid >> 1, seg = tid & 1;
        const __half* gq = qk + (row_base + qt * 128 + r) * (2 * H_) + qoff + seg * 32;
        const uint32_t sq = smem_u32(Qs) + r * 128 + ((seg ^ (r & 1)) << 6);
#pragma unroll
        for (int j = 0; j < 4; j++) CP_ASYNC16(sq + j * 16, gq + j * 8);
        CP_COMMIT();
    }
    issueKV(0);
    asm volatile("cp.async.wait_group 1;" ::: "memory");   // Q complete
    __syncthreads();

    const int qrow = wid * 16 + gID;
    uint4 qa[2], qb[2];
#pragma unroll
    for (int c = 0; c < 2; c++) {
        qa[c] = *(const uint4*)(Qs + qrow * 128       + ((c ^ (qrow & 1)) << 6) + tIG * 16);
        qb[c] = *(const uint4*)(Qs + (qrow + 8) * 128 + ((c ^ (qrow & 1)) << 6) + tIG * 16);
    }

    float m0 = -1e30f, m1 = -1e30f, l0 = 0.f, l1 = 0.f;
    float oacc[8][4];
#pragma unroll
    for (int i = 0; i < 8; i++)
#pragma unroll
        for (int j = 0; j < 4; j++) oacc[i][j] = 0.f;

    const float scale = 0.125f;
    const int NT = S_ / 64;

    for (int kt = 0; kt < NT; kt++) {
        __syncthreads();                         // all warps done with iter kt-1
        if (kt + 1 < NT) {
            issueKV(kt + 1);
            asm volatile("cp.async.wait_group 1;" ::: "memory");  // kt complete
        } else {
            asm volatile("cp.async.wait_group 0;" ::: "memory");
        }
        __syncthreads();

        const char* Ks = KsB + (kt & 1) * 8192;
        const char* VT = VTB + (kt & 1) * 8192;

        // --- S = Q @ K^T ---
        float sacc[8][4];
#pragma unroll
        for (int i = 0; i < 8; i++)
#pragma unroll
            for (int j = 0; j < 4; j++) sacc[i][j] = 0.f;

#pragma unroll
        for (int c = 0; c < 2; c++) {
            const uint32_t aa0[4] = {qa[c].x, qb[c].x, qa[c].y, qb[c].y};
            const uint32_t aa1[4] = {qa[c].z, qb[c].z, qa[c].w, qb[c].w};
#pragma unroll
            for (int nt = 0; nt < 8; nt++) {
                const int rB = nt * 8 + gID;
                const uint4 kv8 = *(const uint4*)(Ks + rB * 128 + ((c ^ (rB & 1)) << 6) + tIG * 16);
                const uint32_t bb0[2] = {kv8.x, kv8.y};
                const uint32_t bb1[2] = {kv8.z, kv8.w};
                mma_f16(sacc[nt], aa0, bb0);
                mma_f16(sacc[nt], aa1, bb1);
            }
        }

        // --- online softmax ---
        float mx0 = -1e30f, mx1 = -1e30f;
#pragma unroll
        for (int nt = 0; nt < 8; nt++) {
            mx0 = fmaxf(mx0, fmaxf(sacc[nt][0], sacc[nt][1]));
            mx1 = fmaxf(mx1, fmaxf(sacc[nt][2], sacc[nt][3]));
        }
        mx0 = fmaxf(mx0, __shfl_xor_sync(0xffffffffu, mx0, 1));
        mx0 = fmaxf(mx0, __shfl_xor_sync(0xffffffffu, mx0, 2));
        mx1 = fmaxf(mx1, __shfl_xor_sync(0xffffffffu, mx1, 1));
        mx1 = fmaxf(mx1, __shfl_xor_sync(0xffffffffu, mx1, 2));

        const float mn0 = fmaxf(m0, mx0 * scale);
        const float mn1 = fmaxf(m1, mx1 * scale);
        const float corr0 = __expf(m0 - mn0);
        const float corr1 = __expf(m1 - mn1);

        float sum0 = 0.f, sum1 = 0.f;
#pragma unroll
        for (int nt = 0; nt < 8; nt++) {
            float p0 = h_round(__expf(sacc[nt][0] * scale - mn0));
            float p1 = h_round(__expf(sacc[nt][1] * scale - mn0));
            float p2 = h_round(__expf(sacc[nt][2] * scale - mn1));
            float p3 = h_round(__expf(sacc[nt][3] * scale - mn1));
            sum0 += p0 + p1; sum1 += p2 + p3;
            sacc[nt][0] = p0; sacc[nt][1] = p1; sacc[nt][2] = p2; sacc[nt][3] = p3;
        }
        sum0 += __shfl_xor_sync(0xffffffffu, sum0, 1);
        sum0 += __shfl_xor_sync(0xffffffffu, sum0, 2);
        sum1 += __shfl_xor_sync(0xffffffffu, sum1, 1);
        sum1 += __shfl_xor_sync(0xffffffffu, sum1, 2);

        l0 = l0 * corr0 + sum0; m0 = mn0;
        l1 = l1 * corr1 + sum1; m1 = mn1;
#pragma unroll
        for (int nt = 0; nt < 8; nt++) {
            oacc[nt][0] *= corr0; oacc[nt][1] *= corr0;
            oacc[nt][2] *= corr1; oacc[nt][3] *= corr1;
        }

        // --- write P (fp16, ph-perm kv, parity swizzle) ---
#pragma unroll
        for (int nt = 0; nt < 8; nt++) {
            const int c = nt * 8 + tIG * 2;
            const int cblk = c >> 5;
            const int phc = ph(c) & 31;
            *(__half2*)(Ps + qrow * 128 + ((cblk ^ (qrow & 1)) << 6) + phc * 2) =
                __floats2half2_rn(sacc[nt][0], sacc[nt][1]);
            *(__half2*)(Ps + (qrow + 8) * 128 + ((cblk ^ (qrow & 1)) << 6) + phc * 2) =
                __floats2half2_rn(sacc[nt][2], sacc[nt][3]);
        }
        __syncwarp();

        // --- O += P @ V ---
#pragma unroll
        for (int c = 0; c < 2; c++) {
            const uint4 pa = *(const uint4*)(Ps + qrow * 128       + ((c ^ (qrow & 1)) << 6) + tIG * 16);
            const uint4 pb = *(const uint4*)(Ps + (qrow + 8) * 128 + ((c ^ (qrow & 1)) << 6) + tIG * 16);
            const uint32_t aa0[4] = {pa.x, pb.x, pa.y, pb.y};
            const uint32_t aa1[4] = {pa.z, pb.z, pa.w, pb.w};
#pragma unroll
            for (int nt = 0; nt < 8; nt++) {
                const int rV = nt * 8 + gID;
                const uint4 vv = *(const uint4*)(VT + rV * 128 + ((c ^ (rV & 1)) << 6) + tIG * 16);
                const uint32_t bb0[2] = {vv.x, vv.y};
                const uint32_t bb1[2] = {vv.z, vv.w};
                mma_f16(oacc[nt], aa0, bb0);
                mma_f16(oacc[nt], aa1, bb1);
            }
        }
    }

    // --- write O as fp16 ph-permuted (feeds Wo GEMM) ---
    const float il0 = 1.f / l0, il1 = 1.f / l1;
    __half* orow0 = O + (row_base + qt * 128 + qrow) * H_;
    __half* orow1 = O + (row_base + qt * 128 + qrow + 8) * H_;
#pragma unroll
    for (int nt = 0; nt < 8; nt++) {
        const int c = h * HD_ + nt * 8 + tIG * 2;
        const int pc = ph(c);
        *(__half2*)(orow0 + pc) = __floats2half2_rn(oacc[nt][0] * il0, oacc[nt][1] * il0);
        *(__half2*)(orow1 + pc) = __floats2half2_rn(oacc[nt][2] * il1, oacc[nt][3] * il1);
    }
}

// ---------------------------------------------------------------------------
// Launch
// ---------------------------------------------------------------------------
extern "C" void kernel_launch(void* const* d_in, const int* in_sizes, int n_in,
                              void* d_out, int out_size)
{
    const float* x     = (const float*)d_in[0];
    const float* ln1_w = (const float*)d_in[1];
    const float* ln1_b = (const float*)d_in[2];
    const float* Wqkv  = (const float*)d_in[3];
    const float* bqkv  = (const float*)d_in[4];
    const float* Wo    = (const float*)d_in[5];
    const float* bo    = (const float*)d_in[6];
    const float* ln2_w = (const float*)d_in[7];
    const float* ln2_b = (const float*)d_in[8];
    const float* fc1_w = (const float*)d_in[9];
    const float* fc1_b = (const float*)d_in[10];
    const float* fc2_w = (const float*)d_in[11];
    const float* fc2_b = (const float*)d_in[12];
    float* out = (float*)d_out;

    __half *h, *qk, *v, *vt, *o, *h2, *a, *wqkvT, *woT, *w1T, *w2T;
    float *x2;
    cudaGetSymbolAddress((void**)&h,   g_h);
    cudaGetSymbolAddress((void**)&qk,  g_qk);
    cudaGetSymbolAddress((void**)&v,   g_v);
    cudaGetSymbolAddress((void**)&vt,  g_vt);
    cudaGetSymbolAddress((void**)&o,   g_o);
    cudaGetSymbolAddress((void**)&x2,  g_x2);
    cudaGetSymbolAddress((void**)&h2,  g_h2);
    cudaGetSymbolAddress((void**)&a,   g_a);
    cudaGetSymbolAddress((void**)&wqkvT, g_wqkvT);
    cudaGetSymbolAddress((void**)&woT,   g_woT);
    cudaGetSymbolAddress((void**)&w1T,   g_w1T);
    cudaGetSymbolAddress((void**)&w2T,   g_w2T);

    cudaFuncSetAttribute(gemm_mma,
                         cudaFuncAttributeMaxDynamicSharedMemorySize, GEMM_SMEM);
    cudaFuncSetAttribute(attn_mma,
                         cudaFuncAttributeMaxDynamicSharedMemorySize, ATTN_SMEM);

    // 0) weight prepass: transpose + fp16 + ph-permute
    wtrans<<<dim3(QKV_N / 32, H_ / 32), 256>>>(Wqkv, wqkvT, H_, QKV_N);
    wtrans<<<dim3(H_ / 32,    H_ / 32), 256>>>(Wo,   woT,   H_, H_);
    wtrans<<<dim3(E_ / 32,    H_ / 32), 256>>>(fc1_w, w1T,  H_, E_);
    wtrans<<<dim3(H_ / 32,    E_ / 32), 256>>>(fc2_w, w2T,  E_, H_);

    // 1) LN1 (fp16 ph out)
    ln_kernel<<<M_, 256>>>(x, ln1_w, ln1_b, h);
    // 2) QKV projection (mode 3: Q,K -> qk; V plain -> v)
    gemm_mma<<<dim3(QKV_N / 128, M_ / 128), 256, GEMM_SMEM>>>(
        h, wqkvT, bqkv, nullptr, nullptr, qk, v, M_, QKV_N, H_, 3);
    // 2b) V transpose (coalesced)
    vtrans<<<dim3(S_ / 64, B_ * NH_), 256>>>(v, vt);
    // 3) attention (fp16 tensor cores, Q-tile 128, 2-stage pipeline)
    attn_mma<<<dim3(S_ / 128, B_ * NH_), 256, ATTN_SMEM>>>(qk, vt, o);
    // 4) Wo + residual (fp32 out)
    gemm_mma<<<dim3(H_ / 128, M_ / 128), 256, GEMM_SMEM>>>(
        o, woT, bo, x, x2, nullptr, nullptr, M_, H_, H_, 1);
    // 5) LN2 (fp16 ph out)
    ln_kernel<<<M_, 256>>>(x2, ln2_w, ln2_b, h2);
    // 6) FC1 + GELU (fp16 ph out)
    gemm_mma<<<dim3(E_ / 128, M_ / 128), 256, GEMM_SMEM>>>(
        h2, w1T, fc1_b, nullptr, nullptr, a, nullptr, M_, E_, H_, 2);
    // 7) FC2 + residual -> out (fp32)
    gemm_mma<<<dim3(H_ / 128, M_ / 128), 256, GEMM_SMEM>>>(
        a, w2T, fc2_b, x2, out, nullptr, nullptr, M_, H_, E_, 1);
}

// round 15
// speedup vs baseline: 2.0610x; 1.0214x over previous
#include <cuda_runtime.h>
#include <cuda_fp16.h>
#include <cstdint>
#include <math.h>

// ---------------------------------------------------------------------------
// Problem constants
// ---------------------------------------------------------------------------
#define B_   4
#define S_   2048
#define H_   1024
#define NH_  16
#define HD_  64
#define E_   4096
#define M_   (B_ * S_)          // 8192 tokens
#define QKV_N (3 * H_)          // 3072

// ---------------------------------------------------------------------------
// Scratch (device globals — no allocation allowed)
// ---------------------------------------------------------------------------
__device__ __half g_h  [M_ * H_];       // ln1 output (fp16, ph-perm)
__device__ __half g_qk [M_ * 2 * H_];   // Q,K fp16 ph-perm  [M][2048]
__device__ __half g_v  [M_ * H_];       // V fp16 plain rows [M][1024]
__device__ __half g_vt [64 * 64 * S_];  // V^T fp16: [bh][d][s], s ph-perm
__device__ __half g_o  [M_ * H_];       // attention output (fp16, ph-perm)
__device__ float  g_x2 [M_ * H_];       // x + attn@Wo + bo (plain fp32)
__device__ __half g_h2 [M_ * H_];       // ln2 output (fp16, ph-perm)
__device__ __half g_a  [M_ * E_];       // gelu(fc1) (fp16, ph-perm)
// transposed fp16 weights: [N][K], ph-permuted
__device__ __half g_wqkvT[QKV_N * H_];
__device__ __half g_woT  [H_ * H_];
__device__ __half g_w1T  [E_ * H_];
__device__ __half g_w2T  [H_ * E_];

// ---------------------------------------------------------------------------
// Helpers
// ---------------------------------------------------------------------------
__device__ __forceinline__ uint32_t smem_u32(const void* p) {
    uint32_t a;
    asm("{ .reg .u64 t; cvta.to.shared.u64 t, %1; cvt.u32.u64 %0, t; }"
        : "=r"(a) : "l"(p));
    return a;
}
// fp16 permutation within 32-blocks: thread tIG's halves {2t,2t+1,2t+8,2t+9}
// of both k16 sub-blocks land contiguously in its 16B LDS.128 slice.
__device__ __forceinline__ int ph(int k) {
    const int kk  = k & 15;
    const int blk = (k >> 4) & 1;
    const int o   = kk & 1;
    const int g   = (kk >> 1) & 3;
    const int w   = ((kk >> 3) << 1) | o;
    return (k & ~31) | (g * 8 + blk * 4 + w);
}
__device__ __forceinline__ float h_round(float x) {
    return __half2float(__float2half_rn(x));
}
__device__ __forceinline__ uint32_t pack_h2(float a, float b) {
    __half2 h = __floats2half2_rn(a, b);
    return *(uint32_t*)&h;
}

__device__ __forceinline__ void mma_f16(float* c, const uint32_t* a, const uint32_t* b) {
    asm volatile(
        "mma.sync.aligned.m16n8k16.row.col.f32.f16.f16.f32 "
        "{%0,%1,%2,%3}, {%4,%5,%6,%7}, {%8,%9}, {%0,%1,%2,%3};"
        : "+f"(c[0]), "+f"(c[1]), "+f"(c[2]), "+f"(c[3])
        : "r"(a[0]), "r"(a[1]), "r"(a[2]), "r"(a[3]), "r"(b[0]), "r"(b[1]));
}

#define CP_ASYNC16(saddr, gptr) \
    asm volatile("cp.async.cg.shared.global [%0], [%1], 16;" \
        :: "r"(saddr), "l"(gptr) : "memory")
#define CP_COMMIT() asm volatile("cp.async.commit_group;" ::: "memory")

// ---------------------------------------------------------------------------
// Fused weight transpose + fp16 + ph-permute for ALL four weights.
// Linear-block decode: QKV(3072) | Wo(1024) | FC1(4096) | FC2(4096)
// ---------------------------------------------------------------------------
__global__ __launch_bounds__(256) void wtrans_all(
    const float* __restrict__ W0, __half* __restrict__ T0,   // QKV K=1024 N=3072
    const float* __restrict__ W1, __half* __restrict__ T1,   // Wo  K=1024 N=1024
    const float* __restrict__ W2, __half* __restrict__ T2,   // FC1 K=1024 N=4096
    const float* __restrict__ W3, __half* __restrict__ T3)   // FC2 K=4096 N=1024
{
    const int bid = blockIdx.x;
    const float* W; __half* WT; int K, N, nx, local;
    if (bid < 3072)      { W = W0; WT = T0; K = 1024; N = 3072; nx = 96;  local = bid; }
    else if (bid < 4096) { W = W1; WT = T1; K = 1024; N = 1024; nx = 32;  local = bid - 3072; }
    else if (bid < 8192) { W = W2; WT = T2; K = 1024; N = 4096; nx = 128; local = bid - 4096; }
    else                 { W = W3; WT = T3; K = 4096; N = 1024; nx = 32;  local = bid - 8192; }
    const int n0 = (local % nx) * 32, k0 = (local / nx) * 32;

    __shared__ float t[32][33];
    const int tx = threadIdx.x & 31, ty = threadIdx.x >> 5;
#pragma unroll
    for (int r = 0; r < 4; r++)
        t[ty + 8 * r][tx] = W[(size_t)(k0 + ty + 8 * r) * N + n0 + tx];
    __syncthreads();
#pragma unroll
    for (int r = 0; r < 4; r++) {
        const int n = n0 + ty + 8 * r;
        const int k = k0 + tx;
        WT[(size_t)n * K + ph(k)] = __float2half_rn(t[tx][ty + 8 * r]);
    }
}

// ---------------------------------------------------------------------------
// V transpose: g_v [M][1024] plain -> g_vt [bh][d][s] (s ph-perm within 32)
// ---------------------------------------------------------------------------
__global__ __launch_bounds__(256) void vtrans(
    const __half* __restrict__ V, __half* __restrict__ VT)
{
    __shared__ __half tile[64][72];
    const int kt = blockIdx.x, bh = blockIdx.y;
    const int b = bh >> 4, h = bh & 15;
    const size_t row_base = (size_t)b * S_;
    const int t = threadIdx.x;

    {
        const int srow = t >> 2, seg = t & 3;
        const uint4* src = (const uint4*)(V + (row_base + kt * 64 + srow) * H_ + h * 64 + seg * 16);
        *(uint4*)&tile[srow][seg * 16]     = src[0];
        *(uint4*)&tile[srow][seg * 16 + 8] = src[1];
    }
    __syncthreads();
    if (t < 128) {
        const int d = t >> 1, blk = t & 1;
        __half buf[32];
#pragma unroll
        for (int i = 0; i < 32; i++)
            buf[ph(i)] = tile[blk * 32 + i][d];
        uint4* dst = (uint4*)(VT + ((size_t)bh * 64 + d) * S_ + kt * 64 + blk * 32);
        const uint4* bsrc = (const uint4*)buf;
#pragma unroll
        for (int j = 0; j < 4; j++) dst[j] = bsrc[j];
    }
}

// ---------------------------------------------------------------------------
// FP16 tensor-core GEMM (unchanged round-14 structure).
// ---------------------------------------------------------------------------
#define STAGE_BYTES 32768                // A 16KB + B 16KB
#define GEMM_SMEM   (3 * STAGE_BYTES)    // 98304 per CTA

__global__ __launch_bounds__(256, 2) void gemm_mma(
    const __half* __restrict__ A, const __half* __restrict__ BT,
    const float* __restrict__ bias, const float* __restrict__ R,
    float* __restrict__ C, __half* __restrict__ Ch, __half* __restrict__ Vt,
    int M, int N, int K, int mode)
{
    extern __shared__ char smem[];
    const int tid = threadIdx.x;
    const int wid = tid >> 5, lane = tid & 31;
    const int gID = lane >> 2, tIG = lane & 3;
    const int warp_m = wid & 1, warp_n = wid >> 1;   // 2 x 4
    const int brow = blockIdx.y * 128, bcol = blockIdx.x * 128;
    const uint32_t sb = smem_u32(smem);

    const int lrow = tid >> 1;
    const int lseg = tid & 1;
    const __half* Ag = A  + (size_t)(brow + lrow) * K + lseg * 32;
    const __half* Bg = BT + (size_t)(bcol + lrow) * K + lseg * 32;
    const uint32_t aoff = (uint32_t)(lrow * 128 + ((lseg ^ (lrow & 1)) << 6));
    const uint32_t boff = aoff + 16384;

    float acc[4][4][4];
#pragma unroll
    for (int i = 0; i < 4; i++)
#pragma unroll
        for (int j = 0; j < 4; j++)
#pragma unroll
            for (int t = 0; t < 4; t++) acc[i][j][t] = 0.f;

    const int nt_tiles = K >> 6;

    auto issue = [&](int kt) {
        const uint32_t st = sb + (uint32_t)(kt % 3) * STAGE_BYTES;
        const __half* ga = Ag + kt * 64;
        const __half* gb = Bg + kt * 64;
#pragma unroll
        for (int i = 0; i < 4; i++) {
            CP_ASYNC16(st + aoff + i * 16, ga + i * 8);
            CP_ASYNC16(st + boff + i * 16, gb + i * 8);
        }
        CP_COMMIT();
    };

    issue(0); issue(1);

    const int m_base = warp_m * 64;
    const int n_base = warp_n * 32;

    for (int kt = 0; kt < nt_tiles; kt++) {
        if (kt + 1 < nt_tiles) asm volatile("cp.async.wait_group 1;" ::: "memory");
        else                   asm volatile("cp.async.wait_group 0;" ::: "memory");
        __syncthreads();
        if (kt + 2 < nt_tiles) issue(kt + 2);

        const char* stage = smem + (size_t)(kt % 3) * STAGE_BYTES;
        const uint32_t* as = (const uint32_t*)stage;
        const uint32_t* bs = as + 4096;

#pragma unroll
        for (int c = 0; c < 2; c++) {
            uint4 alow[4], ahigh[4], bv[4];
#pragma unroll
            for (int mt = 0; mt < 4; mt++) {
                const int r0 = m_base + mt * 16 + gID;
                const uint32_t* p = as + r0 * 32 + ((c ^ (r0 & 1)) << 4) + tIG * 4;
                alow[mt]  = *(const uint4*)p;
                ahigh[mt] = *(const uint4*)(p + 256);
            }
#pragma unroll
            for (int nt = 0; nt < 4; nt++) {
                const int rB = n_base + nt * 8 + gID;
                bv[nt] = *(const uint4*)(bs + rB * 32 + ((c ^ (rB & 1)) << 4) + tIG * 4);
            }
#pragma unroll
            for (int mt = 0; mt < 4; mt++) {
                const uint32_t aa0[4] = {alow[mt].x, ahigh[mt].x, alow[mt].y, ahigh[mt].y};
                const uint32_t aa1[4] = {alow[mt].z, ahigh[mt].z, alow[mt].w, ahigh[mt].w};
#pragma unroll
                for (int nt = 0; nt < 4; nt++) {
                    const uint32_t bb0[2] = {bv[nt].x, bv[nt].y};
                    const uint32_t bb1[2] = {bv[nt].z, bv[nt].w};
                    mma_f16(acc[mt][nt], aa0, bb0);
                    mma_f16(acc[mt][nt], aa1, bb1);
                }
            }
        }
    }

    // --- epilogue ---
#pragma unroll
    for (int mt = 0; mt < 4; mt++) {
#pragma unroll
        for (int half_ = 0; half_ < 2; half_++) {
            const int row = brow + m_base + mt * 16 + gID + half_ * 8;
            float* crow = C + (size_t)row * N;
            const float* rrow = (mode == 1) ? (R + (size_t)row * N) : nullptr;
#pragma unroll
            for (int nt = 0; nt < 4; nt++) {
                const int col = bcol + n_base + nt * 8 + tIG * 2;
                float v0 = acc[mt][nt][half_ * 2 + 0];
                float v1 = acc[mt][nt][half_ * 2 + 1];
                const float2 bb = *(const float2*)(bias + col);
                v0 += bb.x; v1 += bb.y;
                if (mode == 1) {
                    const float2 rr = *(const float2*)(rrow + col);
                    v0 += rr.x; v1 += rr.y;
                    *(float2*)(crow + col) = make_float2(v0, v1);
                } else if (mode == 2) {
                    v0 = 0.5f * v0 * (1.f + erff(v0 * 0.70710678118654752f));
                    v1 = 0.5f * v1 * (1.f + erff(v1 * 0.70710678118654752f));
                    *(__half2*)(Ch + (size_t)row * N + ph(col)) =
                        __floats2half2_rn(v0, v1);
                } else { // mode 3: Q,K -> Ch [M][2048]; V plain -> Vt [M][1024]
                    if (col < 2 * H_) {
                        __half* chrow = Ch + (size_t)row * (2 * H_);
                        *(__half2*)(chrow + ph(col)) = __floats2half2_rn(v0, v1);
                    } else {
                        *(__half2*)(Vt + (size_t)row * H_ + (col - 2 * H_)) =
                            __floats2half2_rn(v0, v1);
                    }
                }
            }
        }
    }
}

// ---------------------------------------------------------------------------
// LayerNorm: one block per row of 1024; output fp16, ph-permuted
// ---------------------------------------------------------------------------
__global__ __launch_bounds__(256) void ln_kernel(
    const float* __restrict__ x, const float* __restrict__ w,
    const float* __restrict__ b, __half* __restrict__ out)
{
    const int row = blockIdx.x;
    const int tid = threadIdx.x;
    const float* xr = x + (size_t)row * H_;

    float v[4];
    float s = 0.f, s2 = 0.f;
#pragma unroll
    for (int i = 0; i < 4; i++) {
        v[i] = xr[tid + 256 * i];
        s += v[i];
        s2 += v[i] * v[i];
    }
#pragma unroll
    for (int off = 16; off > 0; off >>= 1) {
        s  += __shfl_xor_sync(0xffffffffu, s,  off);
        s2 += __shfl_xor_sync(0xffffffffu, s2, off);
    }
    __shared__ float red[8], red2[8];
    const int wid = tid >> 5, lane = tid & 31;
    if (lane == 0) { red[wid] = s; red2[wid] = s2; }
    __syncthreads();
    if (tid < 32) {
        float a = (tid < 8) ? red[tid]  : 0.f;
        float c = (tid < 8) ? red2[tid] : 0.f;
#pragma unroll
        for (int off = 4; off > 0; off >>= 1) {
            a += __shfl_xor_sync(0xffffffffu, a, off);
            c += __shfl_xor_sync(0xffffffffu, c, off);
        }
        if (tid == 0) { red[0] = a; red2[0] = c; }
    }
    __syncthreads();
    const float mu  = red[0] * (1.f / H_);
    const float var = red2[0] * (1.f / H_) - mu * mu;
    const float rstd = rsqrtf(var + 1e-5f);

    __half* orow = out + (size_t)row * H_;
#pragma unroll
    for (int i = 0; i < 4; i++) {
        const int c = tid + 256 * i;
        orow[ph(c)] = __float2half_rn((v[i] - mu) * rstd * w[c] + b[c]);
    }
}

// ---------------------------------------------------------------------------
// FP16 flash attention, Q-tile 128, 3-stage K/V pipeline, ONE sync/iter,
// P kept entirely in registers (sacc layout == PV a-fragment layout).
// Grid (16, 64), 256 threads = 8 warps.
// ---------------------------------------------------------------------------
#define ATTN_SMEM (16384 + 3 * 8192 + 3 * 8192)   // 64KB

__global__ __launch_bounds__(256) void attn_mma(
    const __half* __restrict__ qk, const __half* __restrict__ vt,
    __half* __restrict__ O)
{
    extern __shared__ char asmem[];
    char* Qs  = asmem;             // [128 q rows][128B]
    char* KsB = Qs + 16384;        // 3 x [64 kv rows][128B]
    char* VTB = KsB + 3 * 8192;    // 3 x [64 d rows][128B kv]

    const int qt = blockIdx.x, bh = blockIdx.y;
    const int b = bh >> 4, h = bh & 15;
    const int tid = threadIdx.x, wid = tid >> 5, lane = tid & 31;
    const int gID = lane >> 2, tIG = lane & 3;
    const size_t row_base = (size_t)b * S_;
    const int qoff = h * HD_, koff = H_ + h * HD_;
    const __half* vt_bh = vt + (size_t)bh * 64 * S_;

    auto issueKV = [&](int kt) {
        char* Ks = KsB + (kt % 3) * 8192;
        char* VT = VTB + (kt % 3) * 8192;
        const int r = tid >> 2, q = tid & 3;
        const uint32_t dsto = (uint32_t)(r * 128 + (((q >> 1) ^ (r & 1)) << 6) + (q & 1) * 32);
        const __half* gk = qk + (row_base + kt * 64 + r) * (2 * H_) + koff + q * 16;
        const uint32_t sk = smem_u32(Ks) + dsto;
        CP_ASYNC16(sk,      gk);
        CP_ASYNC16(sk + 16, gk + 8);
        const __half* gv = vt_bh + (size_t)r * S_ + kt * 64 + q * 16;
        const uint32_t sv = smem_u32(VT) + dsto;
        CP_ASYNC16(sv,      gv);
        CP_ASYNC16(sv + 16, gv + 8);
        CP_COMMIT();
    };

    // --- prologue: Q group, then KV0, KV1 ---
    {
        const int r = tid >> 1, seg = tid & 1;
        const __half* gq = qk + (row_base + qt * 128 + r) * (2 * H_) + qoff + seg * 32;
        const uint32_t sq = smem_u32(Qs) + r * 128 + ((seg ^ (r & 1)) << 6);
#pragma unroll
        for (int j = 0; j < 4; j++) CP_ASYNC16(sq + j * 16, gq + j * 8);
        CP_COMMIT();
    }
    issueKV(0);
    issueKV(1);
    asm volatile("cp.async.wait_group 2;" ::: "memory");   // Q complete
    __syncthreads();

    const int qrow = wid * 16 + gID;
    uint4 qa[2], qb[2];
#pragma unroll
    for (int c = 0; c < 2; c++) {
        qa[c] = *(const uint4*)(Qs + qrow * 128       + ((c ^ (qrow & 1)) << 6) + tIG * 16);
        qb[c] = *(const uint4*)(Qs + (qrow + 8) * 128 + ((c ^ (qrow & 1)) << 6) + tIG * 16);
    }

    float m0 = -1e30f, m1 = -1e30f, l0 = 0.f, l1 = 0.f;
    float oacc[8][4];
#pragma unroll
    for (int i = 0; i < 8; i++)
#pragma unroll
        for (int j = 0; j < 4; j++) oacc[i][j] = 0.f;

    const float scale = 0.125f;
    const int NT = S_ / 64;

    for (int kt = 0; kt < NT; kt++) {
        if (kt + 1 < NT) asm volatile("cp.async.wait_group 1;" ::: "memory");
        else             asm volatile("cp.async.wait_group 0;" ::: "memory");
        __syncthreads();             // KV(kt) visible; buffer (kt+2)%3 free
        if (kt + 2 < NT) issueKV(kt + 2);

        const char* Ks = KsB + (kt % 3) * 8192;
        const char* VT = VTB + (kt % 3) * 8192;

        // --- S = Q @ K^T ---
        float sacc[8][4];
#pragma unroll
        for (int i = 0; i < 8; i++)
#pragma unroll
            for (int j = 0; j < 4; j++) sacc[i][j] = 0.f;

#pragma unroll
        for (int c = 0; c < 2; c++) {
            const uint32_t aa0[4] = {qa[c].x, qb[c].x, qa[c].y, qb[c].y};
            const uint32_t aa1[4] = {qa[c].z, qb[c].z, qa[c].w, qb[c].w};
#pragma unroll
            for (int nt = 0; nt < 8; nt++) {
                const int rB = nt * 8 + gID;
                const uint4 kv8 = *(const uint4*)(Ks + rB * 128 + ((c ^ (rB & 1)) << 6) + tIG * 16);
                const uint32_t bb0[2] = {kv8.x, kv8.y};
                const uint32_t bb1[2] = {kv8.z, kv8.w};
                mma_f16(sacc[nt], aa0, bb0);
                mma_f16(sacc[nt], aa1, bb1);
            }
        }

        // --- online softmax ---
        float mx0 = -1e30f, mx1 = -1e30f;
#pragma unroll
        for (int nt = 0; nt < 8; nt++) {
            mx0 = fmaxf(mx0, fmaxf(sacc[nt][0], sacc[nt][1]));
            mx1 = fmaxf(mx1, fmaxf(sacc[nt][2], sacc[nt][3]));
        }
        mx0 = fmaxf(mx0, __shfl_xor_sync(0xffffffffu, mx0, 1));
        mx0 = fmaxf(mx0, __shfl_xor_sync(0xffffffffu, mx0, 2));
        mx1 = fmaxf(mx1, __shfl_xor_sync(0xffffffffu, mx1, 1));
        mx1 = fmaxf(mx1, __shfl_xor_sync(0xffffffffu, mx1, 2));

        const float mn0 = fmaxf(m0, mx0 * scale);
        const float mn1 = fmaxf(m1, mx1 * scale);
        const float corr0 = __expf(m0 - mn0);
        const float corr1 = __expf(m1 - mn1);

        float sum0 = 0.f, sum1 = 0.f;
        uint32_t pr[8][2];
#pragma unroll
        for (int nt = 0; nt < 8; nt++) {
            float p0 = h_round(__expf(sacc[nt][0] * scale - mn0));
            float p1 = h_round(__expf(sacc[nt][1] * scale - mn0));
            float p2 = h_round(__expf(sacc[nt][2] * scale - mn1));
            float p3 = h_round(__expf(sacc[nt][3] * scale - mn1));
            sum0 += p0 + p1; sum1 += p2 + p3;
            pr[nt][0] = pack_h2(p0, p1);   // row qrow,  cols 8nt+2t,+1
            pr[nt][1] = pack_h2(p2, p3);   // row qrow+8
        }
        sum0 += __shfl_xor_sync(0xffffffffu, sum0, 1);
        sum0 += __shfl_xor_sync(0xffffffffu, sum0, 2);
        sum1 += __shfl_xor_sync(0xffffffffu, sum1, 1);
        sum1 += __shfl_xor_sync(0xffffffffu, sum1, 2);

        l0 = l0 * corr0 + sum0; m0 = mn0;
        l1 = l1 * corr1 + sum1; m1 = mn1;
#pragma unroll
        for (int nt = 0; nt < 8; nt++) {
            oacc[nt][0] *= corr0; oacc[nt][1] *= corr0;
            oacc[nt][2] *= corr1; oacc[nt][3] *= corr1;
        }

        // --- O += P @ V, P directly from registers ---
        // a-frag for k16-block j: {pr[2j][0], pr[2j][1], pr[2j+1][0], pr[2j+1][1]}
#pragma unroll
        for (int c = 0; c < 2; c++) {
            uint4 vv[8];
#pragma unroll
            for (int nt = 0; nt < 8; nt++) {
                const int rV = nt * 8 + gID;
                vv[nt] = *(const uint4*)(VT + rV * 128 + ((c ^ (rV & 1)) << 6) + tIG * 16);
            }
#pragma unroll
            for (int jj = 0; jj < 2; jj++) {
                const int j = 2 * c + jj;
                const uint32_t aa[4] = {pr[2 * j][0], pr[2 * j][1],
                                        pr[2 * j + 1][0], pr[2 * j + 1][1]};
#pragma unroll
                for (int nt = 0; nt < 8; nt++) {
                    const uint32_t bb[2] = {jj == 0 ? vv[nt].x : vv[nt].z,
                                            jj == 0 ? vv[nt].y : vv[nt].w};
                    mma_f16(oacc[nt], aa, bb);
                }
            }
        }
    }

    // --- write O as fp16 ph-permuted (feeds Wo GEMM) ---
    const float il0 = 1.f / l0, il1 = 1.f / l1;
    __half* orow0 = O + (row_base + qt * 128 + qrow) * H_;
    __half* orow1 = O + (row_base + qt * 128 + qrow + 8) * H_;
#pragma unroll
    for (int nt = 0; nt < 8; nt++) {
        const int c = h * HD_ + nt * 8 + tIG * 2;
        const int pc = ph(c);
        *(__half2*)(orow0 + pc) = __floats2half2_rn(oacc[nt][0] * il0, oacc[nt][1] * il0);
        *(__half2*)(orow1 + pc) = __floats2half2_rn(oacc[nt][2] * il1, oacc[nt][3] * il1);
    }
}

// ---------------------------------------------------------------------------
// Launch
// ---------------------------------------------------------------------------
extern "C" void kernel_launch(void* const* d_in, const int* in_sizes, int n_in,
                              void* d_out, int out_size)
{
    const float* x     = (const float*)d_in[0];
    const float* ln1_w = (const float*)d_in[1];
    const float* ln1_b = (const float*)d_in[2];
    const float* Wqkv  = (const float*)d_in[3];
    const float* bqkv  = (const float*)d_in[4];
    const float* Wo    = (const float*)d_in[5];
    const float* bo    = (const float*)d_in[6];
    const float* ln2_w = (const float*)d_in[7];
    const float* ln2_b = (const float*)d_in[8];
    const float* fc1_w = (const float*)d_in[9];
    const float* fc1_b = (const float*)d_in[10];
    const float* fc2_w = (const float*)d_in[11];
    const float* fc2_b = (const float*)d_in[12];
    float* out = (float*)d_out;

    __half *h, *qk, *v, *vt, *o, *h2, *a, *wqkvT, *woT, *w1T, *w2T;
    float *x2;
    cudaGetSymbolAddress((void**)&h,   g_h);
    cudaGetSymbolAddress((void**)&qk,  g_qk);
    cudaGetSymbolAddress((void**)&v,   g_v);
    cudaGetSymbolAddress((void**)&vt,  g_vt);
    cudaGetSymbolAddress((void**)&o,   g_o);
    cudaGetSymbolAddress((void**)&x2,  g_x2);
    cudaGetSymbolAddress((void**)&h2,  g_h2);
    cudaGetSymbolAddress((void**)&a,   g_a);
    cudaGetSymbolAddress((void**)&wqkvT, g_wqkvT);
    cudaGetSymbolAddress((void**)&woT,   g_woT);
    cudaGetSymbolAddress((void**)&w1T,   g_w1T);
    cudaGetSymbolAddress((void**)&w2T,   g_w2T);

    cudaFuncSetAttribute(gemm_mma,
                         cudaFuncAttributeMaxDynamicSharedMemorySize, GEMM_SMEM);
    cudaFuncSetAttribute(attn_mma,
                         cudaFuncAttributeMaxDynamicSharedMemorySize, ATTN_SMEM);

    // 0) fused weight prepass
    wtrans_all<<<12288, 256>>>(Wqkv, wqkvT, Wo, woT, fc1_w, w1T, fc2_w, w2T);

    // 1) LN1 (fp16 ph out)
    ln_kernel<<<M_, 256>>>(x, ln1_w, ln1_b, h);
    // 2) QKV projection (mode 3: Q,K -> qk; V plain -> v)
    gemm_mma<<<dim3(QKV_N / 128, M_ / 128), 256, GEMM_SMEM>>>(
        h, wqkvT, bqkv, nullptr, nullptr, qk, v, M_, QKV_N, H_, 3);
    // 2b) V transpose (coalesced)
    vtrans<<<dim3(S_ / 64, B_ * NH_), 256>>>(v, vt);
    // 3) attention (fp16, Q-tile 128, 3-stage pipeline, P-in-regs)
    attn_mma<<<dim3(S_ / 128, B_ * NH_), 256, ATTN_SMEM>>>(qk, vt, o);
    // 4) Wo + residual (fp32 out)
    gemm_mma<<<dim3(H_ / 128, M_ / 128), 256, GEMM_SMEM>>>(
        o, woT, bo, x, x2, nullptr, nullptr, M_, H_, H_, 1);
    // 5) LN2 (fp16 ph out)
    ln_kernel<<<M_, 256>>>(x2, ln2_w, ln2_b, h2);
    // 6) FC1 + GELU (fp16 ph out)
    gemm_mma<<<dim3(E_ / 128, M_ / 128), 256, GEMM_SMEM>>>(
        h2, w1T, fc1_b, nullptr, nullptr, a, nullptr, M_, E_, H_, 2);
    // 7) FC2 + residual -> out (fp32)
    gemm_mma<<<dim3(H_ / 128, M_ / 128), 256, GEMM_SMEM>>>(
        a, w2T, fc2_b, x2, out, nullptr, nullptr, M_, H_, E_, 1);
}

// round 16
// speedup vs baseline: 2.5171x; 1.2213x over previous
#include <cuda_runtime.h>
#include <cuda_fp16.h>
#include <cstdint>
#include <math.h>

// ---------------------------------------------------------------------------
// Problem constants
// ---------------------------------------------------------------------------
#define B_   4
#define S_   2048
#define H_   1024
#define NH_  16
#define HD_  64
#define E_   4096
#define M_   (B_ * S_)          // 8192 tokens
#define QKV_N (3 * H_)          // 3072

// ---------------------------------------------------------------------------
// Scratch (device globals — no allocation allowed)
// ---------------------------------------------------------------------------
__device__ __half g_h  [M_ * H_];       // ln1 output (fp16, ph-perm)
__device__ __half g_qk [M_ * 2 * H_];   // Q,K fp16 ph-perm  [M][2048]
__device__ __half g_v  [M_ * H_];       // V fp16 plain rows [M][1024]
__device__ __half g_vt [64 * 64 * S_];  // V^T fp16: [bh][d][s], s ph-perm
__device__ __half g_o  [M_ * H_];       // attention output (fp16, ph-perm)
__device__ float  g_x2 [M_ * H_];       // x + attn@Wo + bo (plain fp32)
__device__ __half g_h2 [M_ * H_];       // ln2 output (fp16, ph-perm)
__device__ __half g_a  [M_ * E_];       // gelu(fc1) (fp16, ph-perm)
// transposed fp16 weights: [N][K], ph-permuted
__device__ __half g_wqkvT[QKV_N * H_];
__device__ __half g_woT  [H_ * H_];
__device__ __half g_w1T  [E_ * H_];
__device__ __half g_w2T  [H_ * E_];

// ---------------------------------------------------------------------------
// Helpers
// ---------------------------------------------------------------------------
__device__ __forceinline__ uint32_t smem_u32(const void* p) {
    uint32_t a;
    asm("{ .reg .u64 t; cvta.to.shared.u64 t, %1; cvt.u32.u64 %0, t; }"
        : "=r"(a) : "l"(p));
    return a;
}
// fp16 permutation within 32-blocks: thread tIG's halves {2t,2t+1,2t+8,2t+9}
// of both k16 sub-blocks land contiguously in its 16B LDS.128 slice.
__device__ __forceinline__ int ph(int k) {
    const int kk  = k & 15;
    const int blk = (k >> 4) & 1;
    const int o   = kk & 1;
    const int g   = (kk >> 1) & 3;
    const int w   = ((kk >> 3) << 1) | o;
    return (k & ~31) | (g * 8 + blk * 4 + w);
}
__device__ __forceinline__ float h_round(float x) {
    return __half2float(__float2half_rn(x));
}
__device__ __forceinline__ uint32_t pack_h2(float a, float b) {
    __half2 h = __floats2half2_rn(a, b);
    return *(uint32_t*)&h;
}

__device__ __forceinline__ void mma_f16(float* c, const uint32_t* a, const uint32_t* b) {
    asm volatile(
        "mma.sync.aligned.m16n8k16.row.col.f32.f16.f16.f32 "
        "{%0,%1,%2,%3}, {%4,%5,%6,%7}, {%8,%9}, {%0,%1,%2,%3};"
        : "+f"(c[0]), "+f"(c[1]), "+f"(c[2]), "+f"(c[3])
        : "r"(a[0]), "r"(a[1]), "r"(a[2]), "r"(a[3]), "r"(b[0]), "r"(b[1]));
}

#define CP_ASYNC16(saddr, gptr) \
    asm volatile("cp.async.cg.shared.global [%0], [%1], 16;" \
        :: "r"(saddr), "l"(gptr) : "memory")
#define CP_COMMIT() asm volatile("cp.async.commit_group;" ::: "memory")

// ---------------------------------------------------------------------------
// Fused weight transpose + fp16 + ph-permute for ALL four weights.
// ---------------------------------------------------------------------------
__global__ __launch_bounds__(256) void wtrans_all(
    const float* __restrict__ W0, __half* __restrict__ T0,   // QKV K=1024 N=3072
    const float* __restrict__ W1, __half* __restrict__ T1,   // Wo  K=1024 N=1024
    const float* __restrict__ W2, __half* __restrict__ T2,   // FC1 K=1024 N=4096
    const float* __restrict__ W3, __half* __restrict__ T3)   // FC2 K=4096 N=1024
{
    const int bid = blockIdx.x;
    const float* W; __half* WT; int K, N, nx, local;
    if (bid < 3072)      { W = W0; WT = T0; K = 1024; N = 3072; nx = 96;  local = bid; }
    else if (bid < 4096) { W = W1; WT = T1; K = 1024; N = 1024; nx = 32;  local = bid - 3072; }
    else if (bid < 8192) { W = W2; WT = T2; K = 1024; N = 4096; nx = 128; local = bid - 4096; }
    else                 { W = W3; WT = T3; K = 4096; N = 1024; nx = 32;  local = bid - 8192; }
    const int n0 = (local % nx) * 32, k0 = (local / nx) * 32;

    __shared__ float t[32][33];
    const int tx = threadIdx.x & 31, ty = threadIdx.x >> 5;
#pragma unroll
    for (int r = 0; r < 4; r++)
        t[ty + 8 * r][tx] = W[(size_t)(k0 + ty + 8 * r) * N + n0 + tx];
    __syncthreads();
#pragma unroll
    for (int r = 0; r < 4; r++) {
        const int n = n0 + ty + 8 * r;
        const int k = k0 + tx;
        WT[(size_t)n * K + ph(k)] = __float2half_rn(t[tx][ty + 8 * r]);
    }
}

// ---------------------------------------------------------------------------
// V transpose: g_v [M][1024] plain -> g_vt [bh][d][s] (s ph-perm within 32)
// ---------------------------------------------------------------------------
__global__ __launch_bounds__(256) void vtrans(
    const __half* __restrict__ V, __half* __restrict__ VT)
{
    __shared__ __half tile[64][72];
    const int kt = blockIdx.x, bh = blockIdx.y;
    const int b = bh >> 4, h = bh & 15;
    const size_t row_base = (size_t)b * S_;
    const int t = threadIdx.x;

    {
        const int srow = t >> 2, seg = t & 3;
        const uint4* src = (const uint4*)(V + (row_base + kt * 64 + srow) * H_ + h * 64 + seg * 16);
        *(uint4*)&tile[srow][seg * 16]     = src[0];
        *(uint4*)&tile[srow][seg * 16 + 8] = src[1];
    }
    __syncthreads();
    if (t < 128) {
        const int d = t >> 1, blk = t & 1;
        __half buf[32];
#pragma unroll
        for (int i = 0; i < 32; i++)
            buf[ph(i)] = tile[blk * 32 + i][d];
        uint4* dst = (uint4*)(VT + ((size_t)bh * 64 + d) * S_ + kt * 64 + blk * 32);
        const uint4* bsrc = (const uint4*)buf;
#pragma unroll
        for (int j = 0; j < 4; j++) dst[j] = bsrc[j];
    }
}

// ---------------------------------------------------------------------------
// FP16 tensor-core GEMM v6: 128x128 CTA, BK=64, 128 threads, 4 warps (2m x 2n),
// warp tile 64x64 (A replication halved: 32 LDS.128 : 128 HMMA per warp/kt).
// 3-stage cp.async (32KB/stage), 2 CTAs/SM.
// mode 1: bias+residual -> C fp32; mode 2: bias+GELU -> Ch fp16 ph-perm;
// mode 3: Q,K -> Ch [M][2048] ph-perm; V plain -> Vt [M][1024]
// ---------------------------------------------------------------------------
#define STAGE_BYTES 32768                // A 16KB + B 16KB
#define GEMM_SMEM   (3 * STAGE_BYTES)    // 98304 per CTA

__global__ __launch_bounds__(128, 2) void gemm_mma(
    const __half* __restrict__ A, const __half* __restrict__ BT,
    const float* __restrict__ bias, const float* __restrict__ R,
    float* __restrict__ C, __half* __restrict__ Ch, __half* __restrict__ Vt,
    int M, int N, int K, int mode)
{
    extern __shared__ char smem[];
    const int tid = threadIdx.x;
    const int wid = tid >> 5, lane = tid & 31;
    const int gID = lane >> 2, tIG = lane & 3;
    const int warp_m = wid & 1, warp_n = wid >> 1;   // 2 x 2
    const int brow = blockIdx.y * 128, bcol = blockIdx.x * 128;
    const uint32_t sb = smem_u32(smem);

    // loader: 128 threads; base row = tid>>3 (0..15), chunk = tid&7 (16B)
    const int lrow = tid >> 3;
    const int lch  = tid & 7;
    const __half* Ag = A  + (size_t)(brow + lrow) * K + lch * 8;
    const __half* Bg = BT + (size_t)(bcol + lrow) * K + lch * 8;
    const uint32_t loff = (uint32_t)(lrow * 128 + ((((lch >> 2) ^ (lrow & 1)) & 1) << 6) + (lch & 3) * 16);

    float acc[4][8][4];
#pragma unroll
    for (int i = 0; i < 4; i++)
#pragma unroll
        for (int j = 0; j < 8; j++)
#pragma unroll
            for (int t = 0; t < 4; t++) acc[i][j][t] = 0.f;

    const int nt_tiles = K >> 6;

    auto issue = [&](int kt) {
        const uint32_t st = sb + (uint32_t)(kt % 3) * STAGE_BYTES;
        const __half* ga = Ag + kt * 64;
        const __half* gb = Bg + kt * 64;
#pragma unroll
        for (int p = 0; p < 8; p++) {
            CP_ASYNC16(st + loff + p * 2048,         ga + (size_t)(p * 16) * K);
            CP_ASYNC16(st + 16384 + loff + p * 2048, gb + (size_t)(p * 16) * K);
        }
        CP_COMMIT();
    };

    issue(0); issue(1);

    const int m_base = warp_m * 64;
    const int n_base = warp_n * 64;

    for (int kt = 0; kt < nt_tiles; kt++) {
        if (kt + 1 < nt_tiles) asm volatile("cp.async.wait_group 1;" ::: "memory");
        else                   asm volatile("cp.async.wait_group 0;" ::: "memory");
        __syncthreads();
        if (kt + 2 < nt_tiles) issue(kt + 2);

        const char* stage = smem + (size_t)(kt % 3) * STAGE_BYTES;
        const uint32_t* as = (const uint32_t*)stage;
        const uint32_t* bs = as + 4096;

#pragma unroll
        for (int c = 0; c < 2; c++) {
            uint4 alow[4], ahigh[4], bv[8];
#pragma unroll
            for (int mt = 0; mt < 4; mt++) {
                const int r0 = m_base + mt * 16 + gID;
                const uint32_t* p = as + r0 * 32 + ((c ^ (r0 & 1)) << 4) + tIG * 4;
                alow[mt]  = *(const uint4*)p;
                ahigh[mt] = *(const uint4*)(p + 256);
            }
#pragma unroll
            for (int nt = 0; nt < 8; nt++) {
                const int rB = n_base + nt * 8 + gID;
                bv[nt] = *(const uint4*)(bs + rB * 32 + ((c ^ (rB & 1)) << 4) + tIG * 4);
            }
#pragma unroll
            for (int mt = 0; mt < 4; mt++) {
                const uint32_t aa0[4] = {alow[mt].x, ahigh[mt].x, alow[mt].y, ahigh[mt].y};
                const uint32_t aa1[4] = {alow[mt].z, ahigh[mt].z, alow[mt].w, ahigh[mt].w};
#pragma unroll
                for (int nt = 0; nt < 8; nt++) {
                    const uint32_t bb0[2] = {bv[nt].x, bv[nt].y};
                    const uint32_t bb1[2] = {bv[nt].z, bv[nt].w};
                    mma_f16(acc[mt][nt], aa0, bb0);
                    mma_f16(acc[mt][nt], aa1, bb1);
                }
            }
        }
    }

    // --- epilogue ---
#pragma unroll
    for (int mt = 0; mt < 4; mt++) {
#pragma unroll
        for (int half_ = 0; half_ < 2; half_++) {
            const int row = brow + m_base + mt * 16 + gID + half_ * 8;
            float* crow = C + (size_t)row * N;
            const float* rrow = (mode == 1) ? (R + (size_t)row * N) : nullptr;
#pragma unroll
            for (int nt = 0; nt < 8; nt++) {
                const int col = bcol + n_base + nt * 8 + tIG * 2;
                float v0 = acc[mt][nt][half_ * 2 + 0];
                float v1 = acc[mt][nt][half_ * 2 + 1];
                const float2 bb = *(const float2*)(bias + col);
                v0 += bb.x; v1 += bb.y;
                if (mode == 1) {
                    const float2 rr = *(const float2*)(rrow + col);
                    v0 += rr.x; v1 += rr.y;
                    *(float2*)(crow + col) = make_float2(v0, v1);
                } else if (mode == 2) {
                    v0 = 0.5f * v0 * (1.f + erff(v0 * 0.70710678118654752f));
                    v1 = 0.5f * v1 * (1.f + erff(v1 * 0.70710678118654752f));
                    *(__half2*)(Ch + (size_t)row * N + ph(col)) =
                        __floats2half2_rn(v0, v1);
                } else { // mode 3
                    if (col < 2 * H_) {
                        __half* chrow = Ch + (size_t)row * (2 * H_);
                        *(__half2*)(chrow + ph(col)) = __floats2half2_rn(v0, v1);
                    } else {
                        *(__half2*)(Vt + (size_t)row * H_ + (col - 2 * H_)) =
                            __floats2half2_rn(v0, v1);
                    }
                }
            }
        }
    }
}

// ---------------------------------------------------------------------------
// LayerNorm: one block per row of 1024; output fp16, ph-permuted
// ---------------------------------------------------------------------------
__global__ __launch_bounds__(256) void ln_kernel(
    const float* __restrict__ x, const float* __restrict__ w,
    const float* __restrict__ b, __half* __restrict__ out)
{
    const int row = blockIdx.x;
    const int tid = threadIdx.x;
    const float* xr = x + (size_t)row * H_;

    float v[4];
    float s = 0.f, s2 = 0.f;
#pragma unroll
    for (int i = 0; i < 4; i++) {
        v[i] = xr[tid + 256 * i];
        s += v[i];
        s2 += v[i] * v[i];
    }
#pragma unroll
    for (int off = 16; off > 0; off >>= 1) {
        s  += __shfl_xor_sync(0xffffffffu, s,  off);
        s2 += __shfl_xor_sync(0xffffffffu, s2, off);
    }
    __shared__ float red[8], red2[8];
    const int wid = tid >> 5, lane = tid & 31;
    if (lane == 0) { red[wid] = s; red2[wid] = s2; }
    __syncthreads();
    if (tid < 32) {
        float a = (tid < 8) ? red[tid]  : 0.f;
        float c = (tid < 8) ? red2[tid] : 0.f;
#pragma unroll
        for (int off = 4; off > 0; off >>= 1) {
            a += __shfl_xor_sync(0xffffffffu, a, off);
            c += __shfl_xor_sync(0xffffffffu, c, off);
        }
        if (tid == 0) { red[0] = a; red2[0] = c; }
    }
    __syncthreads();
    const float mu  = red[0] * (1.f / H_);
    const float var = red2[0] * (1.f / H_) - mu * mu;
    const float rstd = rsqrtf(var + 1e-5f);

    __half* orow = out + (size_t)row * H_;
#pragma unroll
    for (int i = 0; i < 4; i++) {
        const int c = tid + 256 * i;
        orow[ph(c)] = __float2half_rn((v[i] - mu) * rstd * w[c] + b[c]);
    }
}

// ---------------------------------------------------------------------------
// FP16 flash attention (round-15: Q-tile 128, 3-stage pipeline, P-in-regs).
// ---------------------------------------------------------------------------
#define ATTN_SMEM (16384 + 3 * 8192 + 3 * 8192)   // 64KB

__global__ __launch_bounds__(256) void attn_mma(
    const __half* __restrict__ qk, const __half* __restrict__ vt,
    __half* __restrict__ O)
{
    extern __shared__ char asmem[];
    char* Qs  = asmem;             // [128 q rows][128B]
    char* KsB = Qs + 16384;        // 3 x [64 kv rows][128B]
    char* VTB = KsB + 3 * 8192;    // 3 x [64 d rows][128B kv]

    const int qt = blockIdx.x, bh = blockIdx.y;
    const int b = bh >> 4, h = bh & 15;
    const int tid = threadIdx.x, wid = tid >> 5, lane = tid & 31;
    const int gID = lane >> 2, tIG = lane & 3;
    const size_t row_base = (size_t)b * S_;
    const int qoff = h * HD_, koff = H_ + h * HD_;
    const __half* vt_bh = vt + (size_t)bh * 64 * S_;

    auto issueKV = [&](int kt) {
        char* Ks = KsB + (kt % 3) * 8192;
        char* VT = VTB + (kt % 3) * 8192;
        const int r = tid >> 2, q = tid & 3;
        const uint32_t dsto = (uint32_t)(r * 128 + (((q >> 1) ^ (r & 1)) << 6) + (q & 1) * 32);
        const __half* gk = qk + (row_base + kt * 64 + r) * (2 * H_) + koff + q * 16;
        const uint32_t sk = smem_u32(Ks) + dsto;
        CP_ASYNC16(sk,      gk);
        CP_ASYNC16(sk + 16, gk + 8);
        const __half* gv = vt_bh + (size_t)r * S_ + kt * 64 + q * 16;
        const uint32_t sv = smem_u32(VT) + dsto;
        CP_ASYNC16(sv,      gv);
        CP_ASYNC16(sv + 16, gv + 8);
        CP_COMMIT();
    };

    {
        const int r = tid >> 1, seg = tid & 1;
        const __half* gq = qk + (row_base + qt * 128 + r) * (2 * H_) + qoff + seg * 32;
        const uint32_t sq = smem_u32(Qs) + r * 128 + ((seg ^ (r & 1)) << 6);
#pragma unroll
        for (int j = 0; j < 4; j++) CP_ASYNC16(sq + j * 16, gq + j * 8);
        CP_COMMIT();
    }
    issueKV(0);
    issueKV(1);
    asm volatile("cp.async.wait_group 2;" ::: "memory");
    __syncthreads();

    const int qrow = wid * 16 + gID;
    uint4 qa[2], qb[2];
#pragma unroll
    for (int c = 0; c < 2; c++) {
        qa[c] = *(const uint4*)(Qs + qrow * 128       + ((c ^ (qrow & 1)) << 6) + tIG * 16);
        qb[c] = *(const uint4*)(Qs + (qrow + 8) * 128 + ((c ^ (qrow & 1)) << 6) + tIG * 16);
    }

    float m0 = -1e30f, m1 = -1e30f, l0 = 0.f, l1 = 0.f;
    float oacc[8][4];
#pragma unroll
    for (int i = 0; i < 8; i++)
#pragma unroll
        for (int j = 0; j < 4; j++) oacc[i][j] = 0.f;

    const float scale = 0.125f;
    const int NT = S_ / 64;

    for (int kt = 0; kt < NT; kt++) {
        if (kt + 1 < NT) asm volatile("cp.async.wait_group 1;" ::: "memory");
        else             asm volatile("cp.async.wait_group 0;" ::: "memory");
        __syncthreads();
        if (kt + 2 < NT) issueKV(kt + 2);

        const char* Ks = KsB + (kt % 3) * 8192;
        const char* VT = VTB + (kt % 3) * 8192;

        float sacc[8][4];
#pragma unroll
        for (int i = 0; i < 8; i++)
#pragma unroll
            for (int j = 0; j < 4; j++) sacc[i][j] = 0.f;

#pragma unroll
        for (int c = 0; c < 2; c++) {
            const uint32_t aa0[4] = {qa[c].x, qb[c].x, qa[c].y, qb[c].y};
            const uint32_t aa1[4] = {qa[c].z, qb[c].z, qa[c].w, qb[c].w};
#pragma unroll
            for (int nt = 0; nt < 8; nt++) {
                const int rB = nt * 8 + gID;
                const uint4 kv8 = *(const uint4*)(Ks + rB * 128 + ((c ^ (rB & 1)) << 6) + tIG * 16);
                const uint32_t bb0[2] = {kv8.x, kv8.y};
                const uint32_t bb1[2] = {kv8.z, kv8.w};
                mma_f16(sacc[nt], aa0, bb0);
                mma_f16(sacc[nt], aa1, bb1);
            }
        }

        float mx0 = -1e30f, mx1 = -1e30f;
#pragma unroll
        for (int nt = 0; nt < 8; nt++) {
            mx0 = fmaxf(mx0, fmaxf(sacc[nt][0], sacc[nt][1]));
            mx1 = fmaxf(mx1, fmaxf(sacc[nt][2], sacc[nt][3]));
        }
        mx0 = fmaxf(mx0, __shfl_xor_sync(0xffffffffu, mx0, 1));
        mx0 = fmaxf(mx0, __shfl_xor_sync(0xffffffffu, mx0, 2));
        mx1 = fmaxf(mx1, __shfl_xor_sync(0xffffffffu, mx1, 1));
        mx1 = fmaxf(mx1, __shfl_xor_sync(0xffffffffu, mx1, 2));

        const float mn0 = fmaxf(m0, mx0 * scale);
        const float mn1 = fmaxf(m1, mx1 * scale);
        const float corr0 = __expf(m0 - mn0);
        const float corr1 = __expf(m1 - mn1);

        float sum0 = 0.f, sum1 = 0.f;
        uint32_t pr[8][2];
#pragma unroll
        for (int nt = 0; nt < 8; nt++) {
            float p0 = h_round(__expf(sacc[nt][0] * scale - mn0));
            float p1 = h_round(__expf(sacc[nt][1] * scale - mn0));
            float p2 = h_round(__expf(sacc[nt][2] * scale - mn1));
            float p3 = h_round(__expf(sacc[nt][3] * scale - mn1));
            sum0 += p0 + p1; sum1 += p2 + p3;
            pr[nt][0] = pack_h2(p0, p1);
            pr[nt][1] = pack_h2(p2, p3);
        }
        sum0 += __shfl_xor_sync(0xffffffffu, sum0, 1);
        sum0 += __shfl_xor_sync(0xffffffffu, sum0, 2);
        sum1 += __shfl_xor_sync(0xffffffffu, sum1, 1);
        sum1 += __shfl_xor_sync(0xffffffffu, sum1, 2);

        l0 = l0 * corr0 + sum0; m0 = mn0;
        l1 = l1 * corr1 + sum1; m1 = mn1;
#pragma unroll
        for (int nt = 0; nt < 8; nt++) {
            oacc[nt][0] *= corr0; oacc[nt][1] *= corr0;
            oacc[nt][2] *= corr1; oacc[nt][3] *= corr1;
        }

#pragma unroll
        for (int c = 0; c < 2; c++) {
            uint4 vv[8];
#pragma unroll
            for (int nt = 0; nt < 8; nt++) {
                const int rV = nt * 8 + gID;
                vv[nt] = *(const uint4*)(VT + rV * 128 + ((c ^ (rV & 1)) << 6) + tIG * 16);
            }
#pragma unroll
            for (int jj = 0; jj < 2; jj++) {
                const int j = 2 * c + jj;
                const uint32_t aa[4] = {pr[2 * j][0], pr[2 * j][1],
                                        pr[2 * j + 1][0], pr[2 * j + 1][1]};
#pragma unroll
                for (int nt = 0; nt < 8; nt++) {
                    const uint32_t bb[2] = {jj == 0 ? vv[nt].x : vv[nt].z,
                                            jj == 0 ? vv[nt].y : vv[nt].w};
                    mma_f16(oacc[nt], aa, bb);
                }
            }
        }
    }

    const float il0 = 1.f / l0, il1 = 1.f / l1;
    __half* orow0 = O + (row_base + qt * 128 + qrow) * H_;
    __half* orow1 = O + (row_base + qt * 128 + qrow + 8) * H_;
#pragma unroll
    for (int nt = 0; nt < 8; nt++) {
        const int c = h * HD_ + nt * 8 + tIG * 2;
        const int pc = ph(c);
        *(__half2*)(orow0 + pc) = __floats2half2_rn(oacc[nt][0] * il0, oacc[nt][1] * il0);
        *(__half2*)(orow1 + pc) = __floats2half2_rn(oacc[nt][2] * il1, oacc[nt][3] * il1);
    }
}

// ---------------------------------------------------------------------------
// Launch
// ---------------------------------------------------------------------------
extern "C" void kernel_launch(void* const* d_in, const int* in_sizes, int n_in,
                              void* d_out, int out_size)
{
    const float* x     = (const float*)d_in[0];
    const float* ln1_w = (const float*)d_in[1];
    const float* ln1_b = (const float*)d_in[2];
    const float* Wqkv  = (const float*)d_in[3];
    const float* bqkv  = (const float*)d_in[4];
    const float* Wo    = (const float*)d_in[5];
    const float* bo    = (const float*)d_in[6];
    const float* ln2_w = (const float*)d_in[7];
    const float* ln2_b = (const float*)d_in[8];
    const float* fc1_w = (const float*)d_in[9];
    const float* fc1_b = (const float*)d_in[10];
    const float* fc2_w = (const float*)d_in[11];
    const float* fc2_b = (const float*)d_in[12];
    float* out = (float*)d_out;

    __half *h, *qk, *v, *vt, *o, *h2, *a, *wqkvT, *woT, *w1T, *w2T;
    float *x2;
    cudaGetSymbolAddress((void**)&h,   g_h);
    cudaGetSymbolAddress((void**)&qk,  g_qk);
    cudaGetSymbolAddress((void**)&v,   g_v);
    cudaGetSymbolAddress((void**)&vt,  g_vt);
    cudaGetSymbolAddress((void**)&o,   g_o);
    cudaGetSymbolAddress((void**)&x2,  g_x2);
    cudaGetSymbolAddress((void**)&h2,  g_h2);
    cudaGetSymbolAddress((void**)&a,   g_a);
    cudaGetSymbolAddress((void**)&wqkvT, g_wqkvT);
    cudaGetSymbolAddress((void**)&woT,   g_woT);
    cudaGetSymbolAddress((void**)&w1T,   g_w1T);
    cudaGetSymbolAddress((void**)&w2T,   g_w2T);

    cudaFuncSetAttribute(gemm_mma,
                         cudaFuncAttributeMaxDynamicSharedMemorySize, GEMM_SMEM);
    cudaFuncSetAttribute(attn_mma,
                         cudaFuncAttributeMaxDynamicSharedMemorySize, ATTN_SMEM);

    // 0) fused weight prepass
    wtrans_all<<<12288, 256>>>(Wqkv, wqkvT, Wo, woT, fc1_w, w1T, fc2_w, w2T);

    // 1) LN1 (fp16 ph out)
    ln_kernel<<<M_, 256>>>(x, ln1_w, ln1_b, h);
    // 2) QKV projection (mode 3: Q,K -> qk; V plain -> v)
    gemm_mma<<<dim3(QKV_N / 128, M_ / 128), 128, GEMM_SMEM>>>(
        h, wqkvT, bqkv, nullptr, nullptr, qk, v, M_, QKV_N, H_, 3);
    // 2b) V transpose (coalesced)
    vtrans<<<dim3(S_ / 64, B_ * NH_), 256>>>(v, vt);
    // 3) attention (fp16, Q-tile 128, 3-stage pipeline, P-in-regs)
    attn_mma<<<dim3(S_ / 128, B_ * NH_), 256, ATTN_SMEM>>>(qk, vt, o);
    // 4) Wo + residual (fp32 out)
    gemm_mma<<<dim3(H_ / 128, M_ / 128), 128, GEMM_SMEM>>>(
        o, woT, bo, x, x2, nullptr, nullptr, M_, H_, H_, 1);
    // 5) LN2 (fp16 ph out)
    ln_kernel<<<M_, 256>>>(x2, ln2_w, ln2_b, h2);
    // 6) FC1 + GELU (fp16 ph out)
    gemm_mma<<<dim3(E_ / 128, M_ / 128), 128, GEMM_SMEM>>>(
        h2, w1T, fc1_b, nullptr, nullptr, a, nullptr, M_, E_, H_, 2);
    // 7) FC2 + residual -> out (fp32)
    gemm_mma<<<dim3(H_ / 128, M_ / 128), 128, GEMM_SMEM>>>(
        a, w2T, fc2_b, x2, out, nullptr, nullptr, M_, H_, E_, 1);
}